// round 6
// baseline (speedup 1.0000x reference)
#include <cuda_runtime.h>
#include <cuda_fp16.h>
#include <math.h>
#include <stdint.h>

// Problem constants
#define BB 4
#define CH 4096     // HID
#define SSZ 2048    // S
#define NH 32       // heads
#define HD 128      // head dim

#define BHS 33554432   // BB*CH*SSZ elements
#define WSZ 16777216   // CH*CH elements

// Scratch (allocation-free rule: __device__ globals)
__device__ __half g_qh[BHS];      // Q half [b][ch][s]
__device__ __half g_kh[BHS];      // K half [b][ch][s]
__device__ __half g_vh[BHS];      // V half [b][ch][s]
__device__ __half g_attnTh[BHS];  // attention out, transposed half [b][s][ch]
__device__ __half g_xth[BHS];     // hidden transposed half [b][s][ch]
__device__ __half g_wh[4 * WSZ];  // half Wq,Wk,Wv,Wo (row-major, K-contig)
__device__ float  g_kfb[BHS];     // fallback K dest
__device__ float  g_vfb[BHS];     // fallback V dest

// ===========================================================================
// Helpers
// ===========================================================================
__device__ __forceinline__ uint32_t smem_u32(const void* p) {
    uint32_t a;
    asm("{ .reg .u64 t; cvta.to.shared.u64 t, %1; cvt.u32.u64 %0, t; }"
        : "=r"(a) : "l"(p));
    return a;
}

__device__ __forceinline__ void cp16(uint32_t dst, const void* src) {
    asm volatile("cp.async.cg.shared.global [%0], [%1], 16;"
                 :: "r"(dst), "l"(src) : "memory");
}
#define CP_COMMIT() asm volatile("cp.async.commit_group;" ::: "memory")
#define CP_WAIT(n)  asm volatile("cp.async.wait_group %0;" :: "n"(n) : "memory")

__device__ __forceinline__ void ldsm_x4(uint32_t& r0, uint32_t& r1,
                                        uint32_t& r2, uint32_t& r3, uint32_t addr) {
    asm volatile("ldmatrix.sync.aligned.m8n8.x4.shared.b16 {%0,%1,%2,%3}, [%4];"
                 : "=r"(r0), "=r"(r1), "=r"(r2), "=r"(r3) : "r"(addr));
}

__device__ __forceinline__ void ldsm_x4_t(uint32_t& r0, uint32_t& r1,
                                          uint32_t& r2, uint32_t& r3, uint32_t addr) {
    asm volatile("ldmatrix.sync.aligned.m8n8.x4.trans.shared.b16 {%0,%1,%2,%3}, [%4];"
                 : "=r"(r0), "=r"(r1), "=r"(r2), "=r"(r3) : "r"(addr));
}

// mma m16n8k16 f16 inputs, f32 accumulate
__device__ __forceinline__ void mma_f16(float* d, const uint32_t* a, const uint32_t* b) {
    asm volatile(
        "mma.sync.aligned.m16n8k16.row.col.f32.f16.f16.f32 "
        "{%0,%1,%2,%3}, {%4,%5,%6,%7}, {%8,%9}, {%0,%1,%2,%3};"
        : "+f"(d[0]), "+f"(d[1]), "+f"(d[2]), "+f"(d[3])
        : "r"(a[0]), "r"(a[1]), "r"(a[2]), "r"(a[3]), "r"(b[0]), "r"(b[1]));
}

// ===========================================================================
// Prep kernels
// ===========================================================================
// All four weights in one launch; grid = (8192, 4)
__global__ void round_half4_kernel(
    const float* __restrict__ W0, const float* __restrict__ W1,
    const float* __restrict__ W2, const float* __restrict__ W3,
    __half* __restrict__ Wh)
{
    const float* W = (blockIdx.y == 0) ? W0 : (blockIdx.y == 1) ? W1
                   : (blockIdx.y == 2) ? W2 : W3;
    __half* dst = Wh + (size_t)blockIdx.y * WSZ;
    size_t i = ((size_t)blockIdx.x * 256 + threadIdx.x) * 8;
    float4 v0 = *(const float4*)(W + i);
    float4 v1 = *(const float4*)(W + i + 4);
    __half2 h0 = __floats2half2_rn(v0.x, v0.y);
    __half2 h1 = __floats2half2_rn(v0.z, v0.w);
    __half2 h2 = __floats2half2_rn(v1.x, v1.y);
    __half2 h3 = __floats2half2_rn(v1.z, v1.w);
    uint4 o;
    o.x = *(uint32_t*)&h0; o.y = *(uint32_t*)&h1;
    o.z = *(uint32_t*)&h2; o.w = *(uint32_t*)&h3;
    *(uint4*)(dst + i) = o;
}

// X [b][ch][s] fp32 -> Xt [b][s][ch] half
__global__ void transpose_half_kernel(const float* __restrict__ X, __half* __restrict__ Xt) {
    __shared__ float tile[32][33];
    const int b  = blockIdx.z;
    const int k0 = blockIdx.y * 32;
    const int n0 = blockIdx.x * 32;
    const float* Xb  = X  + (size_t)b * CH * SSZ;
    __half*      Xtb = Xt + (size_t)b * SSZ * CH;
    const int tx = threadIdx.x & 31;
    const int ty = threadIdx.x >> 5;
#pragma unroll
    for (int i = 0; i < 4; i++)
        tile[ty + i * 8][tx] = Xb[(size_t)(k0 + ty + i * 8) * SSZ + n0 + tx];
    __syncthreads();
#pragma unroll
    for (int i = 0; i < 4; i++)
        Xtb[(size_t)(n0 + ty + i * 8) * CH + k0 + tx] =
            __float2half_rn(tile[tx][ty + i * 8]);
}

// ===========================================================================
// fp16 tensor-core GEMM core: Y = A(MxK) @ Bt(NxK)^T + bias
// CTA 128(M) x 256(N), K-chunk 64, 3-stage cp.async, 8 warps (2Mx4N),
// warp tile 64x64 (acc = 128 regs). Stage = A 16KB + B 32KB = 48KB.
// ===========================================================================
#define STAGE_B 49152
#define SMEM_G  (3 * STAGE_B)   // 147456

__device__ __forceinline__ void gemm_core_h(
    const __half* __restrict__ A, const __half* __restrict__ Bb,
    const float* __restrict__ bias, float* __restrict__ Yf,
    __half* __restrict__ Yh, int m0, int n0, char* smem)
{
    const uint32_t sb = smem_u32(smem);
    const int t    = threadIdx.x;
    const int lane = t & 31;
    const int wid  = t >> 5;
    const int wm   = wid >> 2;   // 0..1  (M: 64 each)
    const int wn   = wid & 3;    // 0..3  (N: 64 each)
    const int lr = t >> 3;       // 0..31
    const int lc = t & 7;        // 16B chunk

    float acc[4][8][4];
#pragma unroll
    for (int mt = 0; mt < 4; mt++)
#pragma unroll
        for (int nt = 0; nt < 8; nt++)
#pragma unroll
            for (int x = 0; x < 4; x++) acc[mt][nt][x] = 0.0f;

    auto issue = [&](int chunk) {
        const int stage = chunk % 3;
        const int k0 = chunk * 64;
        const uint32_t As = sb + stage * STAGE_B;
        const uint32_t Bs = As + 16384;
#pragma unroll
        for (int it = 0; it < 4; it++) {
            int m = it * 32 + lr;
            cp16(As + (uint32_t)(m * 128 + ((lc ^ (m & 7)) << 4)),
                 A + (size_t)(m0 + m) * CH + k0 + lc * 8);
        }
#pragma unroll
        for (int it = 0; it < 8; it++) {
            int n = it * 32 + lr;
            cp16(Bs + (uint32_t)(n * 128 + ((lc ^ (n & 7)) << 4)),
                 Bb + (size_t)(n0 + n) * CH + k0 + lc * 8);
        }
        CP_COMMIT();
    };

    issue(0); issue(1); issue(2);

    for (int i = 0; i < 64; i++) {
        CP_WAIT(2);
        __syncthreads();
        const uint32_t As = sb + (i % 3) * STAGE_B;
        const uint32_t Bs = As + 16384;
#pragma unroll
        for (int ks = 0; ks < 4; ks++) {
            uint32_t a[4][4], b[4][4];
#pragma unroll
            for (int mt = 0; mt < 4; mt++) {
                int row = wm * 64 + mt * 16 + (lane & 15);
                int ch  = ks * 2 + (lane >> 4);
                ldsm_x4(a[mt][0], a[mt][1], a[mt][2], a[mt][3],
                        As + row * 128 + ((ch ^ (row & 7)) << 4));
            }
#pragma unroll
            for (int p = 0; p < 4; p++) {
                int row = wn * 64 + p * 16 + ((lane >> 4) << 3) + (lane & 7);
                int ch  = ks * 2 + ((lane >> 3) & 1);
                ldsm_x4(b[p][0], b[p][1], b[p][2], b[p][3],
                        Bs + row * 128 + ((ch ^ (row & 7)) << 4));
            }
#pragma unroll
            for (int mt = 0; mt < 4; mt++)
#pragma unroll
                for (int nt = 0; nt < 8; nt++)
                    mma_f16(acc[mt][nt], a[mt], &b[nt >> 1][(nt & 1) * 2]);
        }
        __syncthreads();
        if (i + 3 < 64) issue(i + 3);
        else CP_COMMIT();
    }

    const int r = lane >> 2;
    const int c = lane & 3;
#pragma unroll
    for (int mt = 0; mt < 4; mt++) {
        int row0 = m0 + wm * 64 + mt * 16 + r;
        float bv0 = bias[row0];
        float bv1 = bias[row0 + 8];
#pragma unroll
        for (int nt = 0; nt < 8; nt++) {
            int col = n0 + wn * 64 + nt * 8 + c * 2;
            float f00 = acc[mt][nt][0] + bv0, f01 = acc[mt][nt][1] + bv0;
            float f10 = acc[mt][nt][2] + bv1, f11 = acc[mt][nt][3] + bv1;
            if (Yf) {
                *(float2*)&Yf[(size_t)row0 * SSZ + col]       = make_float2(f00, f01);
                *(float2*)&Yf[(size_t)(row0 + 8) * SSZ + col] = make_float2(f10, f11);
            }
            if (Yh) {
                __half2 h0 = __floats2half2_rn(f00, f01);
                __half2 h1 = __floats2half2_rn(f10, f11);
                *(__half2*)&Yh[(size_t)row0 * SSZ + col]       = h0;
                *(__half2*)&Yh[(size_t)(row0 + 8) * SSZ + col] = h1;
            }
        }
    }
}

// Fused Q/K/V projections.
__global__ __launch_bounds__(256, 1) void gemm_qkv(
    const __half* __restrict__ Wh, const __half* __restrict__ Xt,
    const float* __restrict__ bq, const float* __restrict__ bk,
    const float* __restrict__ bv,
    __half* __restrict__ Qh, float* __restrict__ Yk, __half* __restrict__ Kh,
    float* __restrict__ Yv, __half* __restrict__ Vh)
{
    extern __shared__ char smem[];
    const int widx = blockIdx.y >> 5;
    const int m0 = (blockIdx.y & 31) * 128;
    const int n0 = blockIdx.x * 256;
    const size_t boff = (size_t)blockIdx.z * CH * SSZ;
    const __half* A = Wh + (size_t)widx * WSZ;
    const __half* Bb = Xt + (size_t)blockIdx.z * SSZ * CH;
    const float* bias = (widx == 0) ? bq : (widx == 1) ? bk : bv;
    float*  Yf = (widx == 0) ? (float*)0 : (widx == 1) ? Yk + boff : Yv + boff;
    __half* Yh = (widx == 0) ? Qh + boff : (widx == 1) ? Kh + boff : Vh + boff;
    gemm_core_h(A, Bb, bias, Yf, Yh, m0, n0, smem);
}

// Single GEMM (output projection), fp32 out only
__global__ __launch_bounds__(256, 1) void gemm_one(
    const __half* __restrict__ A, const __half* __restrict__ Bt,
    const float* __restrict__ bias, float* __restrict__ Y)
{
    extern __shared__ char smem[];
    const int m0 = blockIdx.y * 128;
    const int n0 = blockIdx.x * 256;
    const __half* Bb = Bt + (size_t)blockIdx.z * SSZ * CH;
    float*        Yb = Y  + (size_t)blockIdx.z * CH * SSZ;
    gemm_core_h(A, Bb, bias, Yb, (__half*)0, m0, n0, smem);
}

// ===========================================================================
// Tensor-core attention, 1 CTA per (b,h), 256 threads. (unchanged from R5)
// ===========================================================================
#define STAGE_H 32768
#define ATTN_SMEM 196608
#define OFF_SC 98304
#define OFF_P  163840

__global__ __launch_bounds__(256, 1) void attn_tc(
    const __half* __restrict__ Qh, const __half* __restrict__ Kh,
    const __half* __restrict__ Vh, __half* __restrict__ OT)
{
    extern __shared__ char smem[];
    const uint32_t sb = smem_u32(smem);
    float*  scores = (float*)(smem + OFF_SC);
    __half* Pp     = (__half*)(smem + OFF_P);
    const uint32_t Pb = sb + OFF_P;

    const int bh = blockIdx.x;
    const int b_ = bh >> 5, h_ = bh & 31;
    const size_t hb = ((size_t)b_ * CH + (size_t)h_ * HD) * SSZ;
    const __half* q = Qh + hb;
    const __half* k = Kh + hb;
    const __half* v = Vh + hb;
    __half* oT = OT + (size_t)b_ * SSZ * CH + h_ * HD;

    const int t    = threadIdx.x;
    const int lane = t & 31;
    const int wid  = t >> 5;
    const int wm   = wid >> 2;
    const int wn   = wid & 3;
    const int lr = t >> 3;
    const int lc = t & 7;

    float acc[4][4][4];
#pragma unroll
    for (int mt = 0; mt < 4; mt++)
#pragma unroll
        for (int nt = 0; nt < 4; nt++)
#pragma unroll
            for (int x = 0; x < 4; x++) acc[mt][nt][x] = 0.0f;

    auto issue1 = [&](int chunk) {
        const int stage = chunk % 3;
        const int k0 = chunk * 64;
        const uint32_t As = sb + stage * STAGE_H;
        const uint32_t Bs = As + 16384;
#pragma unroll
        for (int it = 0; it < 4; it++) {
            int m = it * 32 + lr;
            uint32_t sw = (uint32_t)(m * 128 + ((lc ^ (m & 7)) << 4));
            cp16(As + sw, q + (size_t)m * SSZ + k0 + lc * 8);
            cp16(Bs + sw, k + (size_t)m * SSZ + k0 + lc * 8);
        }
        CP_COMMIT();
    };
    issue1(0); issue1(1); issue1(2);

    for (int i = 0; i < 32; i++) {
        CP_WAIT(2);
        __syncthreads();
        const uint32_t As = sb + (i % 3) * STAGE_H;
        const uint32_t Bs = As + 16384;
#pragma unroll
        for (int ks = 0; ks < 4; ks++) {
            uint32_t a[4][4], b[2][4];
#pragma unroll
            for (int mt = 0; mt < 4; mt++) {
                int row = wm * 64 + mt * 16 + (lane & 15);
                int ch  = ks * 2 + (lane >> 4);
                ldsm_x4(a[mt][0], a[mt][1], a[mt][2], a[mt][3],
                        As + row * 128 + ((ch ^ (row & 7)) << 4));
            }
#pragma unroll
            for (int p = 0; p < 2; p++) {
                int row = wn * 32 + p * 16 + ((lane >> 4) << 3) + (lane & 7);
                int ch  = ks * 2 + ((lane >> 3) & 1);
                ldsm_x4(b[p][0], b[p][1], b[p][2], b[p][3],
                        Bs + row * 128 + ((ch ^ (row & 7)) << 4));
            }
#pragma unroll
            for (int mt = 0; mt < 4; mt++)
#pragma unroll
                for (int nt = 0; nt < 4; nt++)
                    mma_f16(acc[mt][nt], a[mt], &b[nt >> 1][(nt & 1) * 2]);
        }
        __syncthreads();
        if (i + 3 < 32) issue1(i + 3);
        else CP_COMMIT();
    }
    CP_WAIT(0);

    {
        const float scale = rsqrtf((float)SSZ);
        const int r = lane >> 2;
        const int c = lane & 3;
#pragma unroll
        for (int mt = 0; mt < 4; mt++) {
            int row0 = wm * 64 + mt * 16 + r;
            int row1 = row0 + 8;
#pragma unroll
            for (int nt = 0; nt < 4; nt++) {
                int col = wn * 32 + nt * 8 + c * 2;
                scores[row0 * 128 + col]     = (col     <= row0) ? acc[mt][nt][0] * scale : -1e30f;
                scores[row0 * 128 + col + 1] = (col + 1 <= row0) ? acc[mt][nt][1] * scale : -1e30f;
                scores[row1 * 128 + col]     = (col     <= row1) ? acc[mt][nt][2] * scale : -1e30f;
                scores[row1 * 128 + col + 1] = (col + 1 <= row1) ? acc[mt][nt][3] * scale : -1e30f;
            }
        }
    }
    __syncthreads();

#pragma unroll 4
    for (int rr = 0; rr < 16; rr++) {
        int row = wid * 16 + rr;
        float v0 = scores[row * 128 + lane];
        float v1 = scores[row * 128 + lane + 32];
        float v2 = scores[row * 128 + lane + 64];
        float v3 = scores[row * 128 + lane + 96];
        float mx = fmaxf(fmaxf(v0, v1), fmaxf(v2, v3));
#pragma unroll
        for (int o = 16; o > 0; o >>= 1)
            mx = fmaxf(mx, __shfl_xor_sync(0xFFFFFFFFu, mx, o));
        float e0 = __expf(v0 - mx), e1 = __expf(v1 - mx);
        float e2 = __expf(v2 - mx), e3 = __expf(v3 - mx);
        float sm = e0 + e1 + e2 + e3;
#pragma unroll
        for (int o = 16; o > 0; o >>= 1)
            sm += __shfl_xor_sync(0xFFFFFFFFu, sm, o);
        float inv = 1.0f / sm;
        float ev[4] = {e0, e1, e2, e3};
#pragma unroll
        for (int j = 0; j < 4; j++) {
            int col = lane + 32 * j;
            int hidx = row * 128 + ((((col >> 3) ^ (row & 7))) << 3) + (col & 7);
            Pp[hidx] = __float2half_rn(ev[j] * inv);
        }
    }

    auto issueV = [&](int nc) {
        const uint32_t Vb = sb + (nc & 1) * 32768;
        const int n0 = nc * 128;
#pragma unroll
        for (int i = 0; i < 8; i++) {
            int idx = i * 256 + t;
            int e = idx >> 4;
            int c = idx & 15;
            cp16(Vb + (uint32_t)(e * 256 + ((c ^ (e & 7)) << 4)),
                 v + (size_t)e * SSZ + n0 + c * 8);
        }
        CP_COMMIT();
    };
    issueV(0);

    __half* OTp = (__half*)(smem + OFF_SC);

    for (int nc = 0; nc < 16; nc++) {
        if (nc + 1 < 16) { issueV(nc + 1); CP_WAIT(1); }
        else             { CP_WAIT(0); }
        __syncthreads();

        const uint32_t Vb = sb + (nc & 1) * 32768;
#pragma unroll
        for (int mt = 0; mt < 4; mt++)
#pragma unroll
            for (int nt = 0; nt < 4; nt++)
#pragma unroll
                for (int x = 0; x < 4; x++) acc[mt][nt][x] = 0.0f;

#pragma unroll
        for (int ks = 0; ks < 8; ks++) {
            uint32_t a[4][4], b[2][4];
#pragma unroll
            for (int mt = 0; mt < 4; mt++) {
                int row = wm * 64 + mt * 16 + (lane & 15);
                int ch  = ks * 2 + (lane >> 4);
                ldsm_x4(a[mt][0], a[mt][1], a[mt][2], a[mt][3],
                        Pb + row * 256 + ((ch ^ (row & 7)) << 4));
            }
#pragma unroll
            for (int p = 0; p < 2; p++) {
                int nb  = wn * 32 + p * 16;
                int grp = lane >> 3;
                int li  = lane & 7;
                int e   = ks * 16 + ((grp & 1) << 3) + li;
                int ncol = nb + ((grp >> 1) << 3);
                ldsm_x4_t(b[p][0], b[p][1], b[p][2], b[p][3],
                          Vb + e * 256 + (((ncol >> 3) ^ (e & 7)) << 4));
            }
#pragma unroll
            for (int mt = 0; mt < 4; mt++)
#pragma unroll
                for (int nt = 0; nt < 4; nt++)
                    mma_f16(acc[mt][nt], a[mt], &b[nt >> 1][(nt & 1) * 2]);
        }

        {
            const int r = lane >> 2;
            const int c = lane & 3;
#pragma unroll
            for (int mt = 0; mt < 4; mt++) {
                int row0 = wm * 64 + mt * 16 + r;
#pragma unroll
                for (int nt = 0; nt < 4; nt++) {
                    int col = wn * 32 + nt * 8 + c * 2;
                    OTp[col * 128 + row0]           = __float2half_rn(acc[mt][nt][0]);
                    OTp[(col + 1) * 128 + row0]     = __float2half_rn(acc[mt][nt][1]);
                    OTp[col * 128 + row0 + 8]       = __float2half_rn(acc[mt][nt][2]);
                    OTp[(col + 1) * 128 + row0 + 8] = __float2half_rn(acc[mt][nt][3]);
                }
            }
        }
        __syncthreads();

        {
            int s  = t >> 1;
            int dp = (t & 1) * 64;
            const uint4* src = (const uint4*)(OTp + s * 128 + dp);
            uint4* dst = (uint4*)(oT + (size_t)(nc * 128 + s) * CH + dp);
#pragma unroll
            for (int u = 0; u < 8; u++) dst[u] = src[u];
        }
        __syncthreads();
    }
}

// ===========================================================================
// Launch
// ===========================================================================
extern "C" void kernel_launch(void* const* d_in, const int* in_sizes, int n_in,
                              void* d_out, int out_size)
{
    const float* hs = (const float*)d_in[0];
    const float* Wq = (const float*)d_in[1];
    const float* bq = (const float*)d_in[2];
    const float* Wk = (const float*)d_in[3];
    const float* bk = (const float*)d_in[4];
    const float* Wv = (const float*)d_in[5];
    const float* bv = (const float*)d_in[6];
    const float* Wo = (const float*)d_in[7];
    const float* bo = (const float*)d_in[8];

    float *kfb, *vfb;
    __half *qh, *kh, *vh, *atbufh, *xth, *wh;
    cudaGetSymbolAddress((void**)&qh,     g_qh);
    cudaGetSymbolAddress((void**)&kh,     g_kh);
    cudaGetSymbolAddress((void**)&vh,     g_vh);
    cudaGetSymbolAddress((void**)&atbufh, g_attnTh);
    cudaGetSymbolAddress((void**)&xth,    g_xth);
    cudaGetSymbolAddress((void**)&wh,     g_wh);
    cudaGetSymbolAddress((void**)&kfb,    g_kfb);
    cudaGetSymbolAddress((void**)&vfb,    g_vfb);

    float* out = (float*)d_out;
    float* kout;
    float* vout;
    if ((long long)out_size >= 3LL * BHS) {
        kout = out + (size_t)BHS;
        vout = out + 2 * (size_t)BHS;
    } else {
        kout = kfb;
        vout = vfb;
    }

    // ---- Prep ----
    round_half4_kernel<<<dim3(WSZ / (256 * 8), 4), 256>>>(Wq, Wk, Wv, Wo, wh);
    transpose_half_kernel<<<dim3(SSZ / 32, CH / 32, BB), 256>>>(hs, xth);

    // ---- Fused Q/K/V projections ----
    cudaFuncSetAttribute(gemm_qkv,
                         cudaFuncAttributeMaxDynamicSharedMemorySize, SMEM_G);
    cudaFuncSetAttribute(gemm_one,
                         cudaFuncAttributeMaxDynamicSharedMemorySize, SMEM_G);
    dim3 blk(256, 1, 1);
    gemm_qkv<<<dim3(SSZ / 256, 96, BB), blk, SMEM_G>>>(
        wh, xth, bq, bk, bv, qh, kout, kh, vout, vh);

    // ---- Tensor-core attention ----
    cudaFuncSetAttribute(attn_tc,
                         cudaFuncAttributeMaxDynamicSharedMemorySize, ATTN_SMEM);
    attn_tc<<<BB * NH, 256, ATTN_SMEM>>>(qh, kh, vh, atbufh);

    // ---- Output projection ----
    gemm_one<<<dim3(SSZ / 256, CH / 128, BB), blk, SMEM_G>>>(
        wh + 3 * (size_t)WSZ, atbufh, bo, out);
}

// round 7
// speedup vs baseline: 1.1242x; 1.1242x over previous
#include <cuda_runtime.h>
#include <cuda_fp16.h>
#include <math.h>
#include <stdint.h>

// Problem constants
#define BB 4
#define CH 4096     // HID
#define SSZ 2048    // S
#define NH 32       // heads
#define HD 128      // head dim

#define BHS 33554432   // BB*CH*SSZ elements
#define WSZ 16777216   // CH*CH elements

// Scratch (allocation-free rule: __device__ globals)
__device__ __half g_qh[BHS];      // Q half [b][ch][s]
__device__ __half g_kh[BHS];      // K half [b][ch][s]
__device__ __half g_vh[BHS];      // V half [b][ch][s]
__device__ __half g_attnTh[BHS];  // attention out, transposed half [b][s][ch]
__device__ __half g_xth[BHS];     // hidden transposed half [b][s][ch]
__device__ __half g_wh[4 * WSZ];  // half Wq,Wk,Wv,Wo (row-major, K-contig)
__device__ float  g_kfb[BHS];     // fallback K dest
__device__ float  g_vfb[BHS];     // fallback V dest

// ===========================================================================
// Helpers
// ===========================================================================
__device__ __forceinline__ uint32_t smem_u32(const void* p) {
    uint32_t a;
    asm("{ .reg .u64 t; cvta.to.shared.u64 t, %1; cvt.u32.u64 %0, t; }"
        : "=r"(a) : "l"(p));
    return a;
}

__device__ __forceinline__ void cp16(uint32_t dst, const void* src) {
    asm volatile("cp.async.cg.shared.global [%0], [%1], 16;"
                 :: "r"(dst), "l"(src) : "memory");
}
#define CP_COMMIT() asm volatile("cp.async.commit_group;" ::: "memory")
#define CP_WAIT(n)  asm volatile("cp.async.wait_group %0;" :: "n"(n) : "memory")

__device__ __forceinline__ void ldsm_x4(uint32_t& r0, uint32_t& r1,
                                        uint32_t& r2, uint32_t& r3, uint32_t addr) {
    asm volatile("ldmatrix.sync.aligned.m8n8.x4.shared.b16 {%0,%1,%2,%3}, [%4];"
                 : "=r"(r0), "=r"(r1), "=r"(r2), "=r"(r3) : "r"(addr));
}

__device__ __forceinline__ void ldsm_x4_t(uint32_t& r0, uint32_t& r1,
                                          uint32_t& r2, uint32_t& r3, uint32_t addr) {
    asm volatile("ldmatrix.sync.aligned.m8n8.x4.trans.shared.b16 {%0,%1,%2,%3}, [%4];"
                 : "=r"(r0), "=r"(r1), "=r"(r2), "=r"(r3) : "r"(addr));
}

// mma m16n8k16 f16 inputs, f32 accumulate
__device__ __forceinline__ void mma_f16(float* d, const uint32_t* a, const uint32_t* b) {
    asm volatile(
        "mma.sync.aligned.m16n8k16.row.col.f32.f16.f16.f32 "
        "{%0,%1,%2,%3}, {%4,%5,%6,%7}, {%8,%9}, {%0,%1,%2,%3};"
        : "+f"(d[0]), "+f"(d[1]), "+f"(d[2]), "+f"(d[3])
        : "r"(a[0]), "r"(a[1]), "r"(a[2]), "r"(a[3]), "r"(b[0]), "r"(b[1]));
}

// ===========================================================================
// Prep kernels
// ===========================================================================
__global__ void round_half4_kernel(
    const float* __restrict__ W0, const float* __restrict__ W1,
    const float* __restrict__ W2, const float* __restrict__ W3,
    __half* __restrict__ Wh)
{
    const float* W = (blockIdx.y == 0) ? W0 : (blockIdx.y == 1) ? W1
                   : (blockIdx.y == 2) ? W2 : W3;
    __half* dst = Wh + (size_t)blockIdx.y * WSZ;
    size_t i = ((size_t)blockIdx.x * 256 + threadIdx.x) * 8;
    float4 v0 = *(const float4*)(W + i);
    float4 v1 = *(const float4*)(W + i + 4);
    __half2 h0 = __floats2half2_rn(v0.x, v0.y);
    __half2 h1 = __floats2half2_rn(v0.z, v0.w);
    __half2 h2 = __floats2half2_rn(v1.x, v1.y);
    __half2 h3 = __floats2half2_rn(v1.z, v1.w);
    uint4 o;
    o.x = *(uint32_t*)&h0; o.y = *(uint32_t*)&h1;
    o.z = *(uint32_t*)&h2; o.w = *(uint32_t*)&h3;
    *(uint4*)(dst + i) = o;
}

// X [b][ch][s] fp32 -> Xt [b][s][ch] half
__global__ void transpose_half_kernel(const float* __restrict__ X, __half* __restrict__ Xt) {
    __shared__ float tile[32][33];
    const int b  = blockIdx.z;
    const int k0 = blockIdx.y * 32;
    const int n0 = blockIdx.x * 32;
    const float* Xb  = X  + (size_t)b * CH * SSZ;
    __half*      Xtb = Xt + (size_t)b * SSZ * CH;
    const int tx = threadIdx.x & 31;
    const int ty = threadIdx.x >> 5;
#pragma unroll
    for (int i = 0; i < 4; i++)
        tile[ty + i * 8][tx] = Xb[(size_t)(k0 + ty + i * 8) * SSZ + n0 + tx];
    __syncthreads();
#pragma unroll
    for (int i = 0; i < 4; i++)
        Xtb[(size_t)(n0 + ty + i * 8) * CH + k0 + tx] =
            __float2half_rn(tile[tx][ty + i * 8]);
}

// ===========================================================================
// fp16 tensor-core GEMM core: Y = A(MxK) @ Bt(NxK)^T + bias
// CTA 128x128, K-chunk 64, 3-stage cp.async, 4 warps (2Mx2N), warp 64x64,
// 128 threads. Stage = A 16KB + B 16KB = 32KB; 3 stages = 96KB; 2 CTA/SM.
// Per k-step per warp: 8 LDSM.x4 : 32 MMA (4:1).
// ===========================================================================
#define STAGE_B 32768
#define SMEM_G  (3 * STAGE_B)   // 98304

__device__ __forceinline__ void gemm_core_h(
    const __half* __restrict__ A, const __half* __restrict__ Bb,
    const float* __restrict__ bias, float* __restrict__ Yf,
    __half* __restrict__ Yh, int m0, int n0, char* smem)
{
    const uint32_t sb = smem_u32(smem);
    const int t    = threadIdx.x;
    const int lane = t & 31;
    const int wid  = t >> 5;     // 0..3
    const int wm   = wid >> 1;   // 0..1  (M: 64 each)
    const int wn   = wid & 1;    // 0..1  (N: 64 each)
    const int lr = t >> 3;       // 0..15
    const int lc = t & 7;        // 16B chunk

    float acc[4][8][4];
#pragma unroll
    for (int mt = 0; mt < 4; mt++)
#pragma unroll
        for (int nt = 0; nt < 8; nt++)
#pragma unroll
            for (int x = 0; x < 4; x++) acc[mt][nt][x] = 0.0f;

    auto issue = [&](int chunk) {
        const int stage = chunk % 3;
        const int k0 = chunk * 64;
        const uint32_t As = sb + stage * STAGE_B;
        const uint32_t Bs = As + 16384;
#pragma unroll
        for (int it = 0; it < 8; it++) {
            int m = it * 16 + lr;
            cp16(As + (uint32_t)(m * 128 + ((lc ^ (m & 7)) << 4)),
                 A + (size_t)(m0 + m) * CH + k0 + lc * 8);
        }
#pragma unroll
        for (int it = 0; it < 8; it++) {
            int n = it * 16 + lr;
            cp16(Bs + (uint32_t)(n * 128 + ((lc ^ (n & 7)) << 4)),
                 Bb + (size_t)(n0 + n) * CH + k0 + lc * 8);
        }
        CP_COMMIT();
    };

    issue(0); issue(1); issue(2);

    for (int i = 0; i < 64; i++) {
        CP_WAIT(2);
        __syncthreads();
        const uint32_t As = sb + (i % 3) * STAGE_B;
        const uint32_t Bs = As + 16384;
#pragma unroll
        for (int ks = 0; ks < 4; ks++) {
            uint32_t a[4][4], b[4][4];
#pragma unroll
            for (int mt = 0; mt < 4; mt++) {
                int row = wm * 64 + mt * 16 + (lane & 15);
                int ch  = ks * 2 + (lane >> 4);
                ldsm_x4(a[mt][0], a[mt][1], a[mt][2], a[mt][3],
                        As + row * 128 + ((ch ^ (row & 7)) << 4));
            }
#pragma unroll
            for (int p = 0; p < 4; p++) {
                int row = wn * 64 + p * 16 + ((lane >> 4) << 3) + (lane & 7);
                int ch  = ks * 2 + ((lane >> 3) & 1);
                ldsm_x4(b[p][0], b[p][1], b[p][2], b[p][3],
                        Bs + row * 128 + ((ch ^ (row & 7)) << 4));
            }
#pragma unroll
            for (int mt = 0; mt < 4; mt++)
#pragma unroll
                for (int nt = 0; nt < 8; nt++)
                    mma_f16(acc[mt][nt], a[mt], &b[nt >> 1][(nt & 1) * 2]);
        }
        __syncthreads();
        if (i + 3 < 64) issue(i + 3);
        else CP_COMMIT();
    }

    const int r = lane >> 2;
    const int c = lane & 3;
#pragma unroll
    for (int mt = 0; mt < 4; mt++) {
        int row0 = m0 + wm * 64 + mt * 16 + r;
        float bv0 = bias[row0];
        float bv1 = bias[row0 + 8];
#pragma unroll
        for (int nt = 0; nt < 8; nt++) {
            int col = n0 + wn * 64 + nt * 8 + c * 2;
            float f00 = acc[mt][nt][0] + bv0, f01 = acc[mt][nt][1] + bv0;
            float f10 = acc[mt][nt][2] + bv1, f11 = acc[mt][nt][3] + bv1;
            if (Yf) {
                *(float2*)&Yf[(size_t)row0 * SSZ + col]       = make_float2(f00, f01);
                *(float2*)&Yf[(size_t)(row0 + 8) * SSZ + col] = make_float2(f10, f11);
            }
            if (Yh) {
                __half2 h0 = __floats2half2_rn(f00, f01);
                __half2 h1 = __floats2half2_rn(f10, f11);
                *(__half2*)&Yh[(size_t)row0 * SSZ + col]       = h0;
                *(__half2*)&Yh[(size_t)(row0 + 8) * SSZ + col] = h1;
            }
        }
    }
}

// Fused Q/K/V projections.
__global__ __launch_bounds__(128, 2) void gemm_qkv(
    const __half* __restrict__ Wh, const __half* __restrict__ Xt,
    const float* __restrict__ bq, const float* __restrict__ bk,
    const float* __restrict__ bv,
    __half* __restrict__ Qh, float* __restrict__ Yk, __half* __restrict__ Kh,
    float* __restrict__ Yv, __half* __restrict__ Vh)
{
    extern __shared__ char smem[];
    const int widx = blockIdx.y >> 5;
    const int m0 = (blockIdx.y & 31) * 128;
    const int n0 = blockIdx.x * 128;
    const size_t boff = (size_t)blockIdx.z * CH * SSZ;
    const __half* A = Wh + (size_t)widx * WSZ;
    const __half* Bb = Xt + (size_t)blockIdx.z * SSZ * CH;
    const float* bias = (widx == 0) ? bq : (widx == 1) ? bk : bv;
    float*  Yf = (widx == 0) ? (float*)0 : (widx == 1) ? Yk + boff : Yv + boff;
    __half* Yh = (widx == 0) ? Qh + boff : (widx == 1) ? Kh + boff : Vh + boff;
    gemm_core_h(A, Bb, bias, Yf, Yh, m0, n0, smem);
}

// Single GEMM (output projection), fp32 out only
__global__ __launch_bounds__(128, 2) void gemm_one(
    const __half* __restrict__ A, const __half* __restrict__ Bt,
    const float* __restrict__ bias, float* __restrict__ Y)
{
    extern __shared__ char smem[];
    const int m0 = blockIdx.y * 128;
    const int n0 = blockIdx.x * 128;
    const __half* Bb = Bt + (size_t)blockIdx.z * SSZ * CH;
    float*        Yb = Y  + (size_t)blockIdx.z * CH * SSZ;
    gemm_core_h(A, Bb, bias, Yb, (__half*)0, m0, n0, smem);
}

// ===========================================================================
// Tensor-core attention, 1 CTA per (b,h), 256 threads. (unchanged from R5)
// ===========================================================================
#define STAGE_H 32768
#define ATTN_SMEM 196608
#define OFF_SC 98304
#define OFF_P  163840

__global__ __launch_bounds__(256, 1) void attn_tc(
    const __half* __restrict__ Qh, const __half* __restrict__ Kh,
    const __half* __restrict__ Vh, __half* __restrict__ OT)
{
    extern __shared__ char smem[];
    const uint32_t sb = smem_u32(smem);
    float*  scores = (float*)(smem + OFF_SC);
    __half* Pp     = (__half*)(smem + OFF_P);
    const uint32_t Pb = sb + OFF_P;

    const int bh = blockIdx.x;
    const int b_ = bh >> 5, h_ = bh & 31;
    const size_t hb = ((size_t)b_ * CH + (size_t)h_ * HD) * SSZ;
    const __half* q = Qh + hb;
    const __half* k = Kh + hb;
    const __half* v = Vh + hb;
    __half* oT = OT + (size_t)b_ * SSZ * CH + h_ * HD;

    const int t    = threadIdx.x;
    const int lane = t & 31;
    const int wid  = t >> 5;
    const int wm   = wid >> 2;
    const int wn   = wid & 3;
    const int lr = t >> 3;
    const int lc = t & 7;

    float acc[4][4][4];
#pragma unroll
    for (int mt = 0; mt < 4; mt++)
#pragma unroll
        for (int nt = 0; nt < 4; nt++)
#pragma unroll
            for (int x = 0; x < 4; x++) acc[mt][nt][x] = 0.0f;

    auto issue1 = [&](int chunk) {
        const int stage = chunk % 3;
        const int k0 = chunk * 64;
        const uint32_t As = sb + stage * STAGE_H;
        const uint32_t Bs = As + 16384;
#pragma unroll
        for (int it = 0; it < 4; it++) {
            int m = it * 32 + lr;
            uint32_t sw = (uint32_t)(m * 128 + ((lc ^ (m & 7)) << 4));
            cp16(As + sw, q + (size_t)m * SSZ + k0 + lc * 8);
            cp16(Bs + sw, k + (size_t)m * SSZ + k0 + lc * 8);
        }
        CP_COMMIT();
    };
    issue1(0); issue1(1); issue1(2);

    for (int i = 0; i < 32; i++) {
        CP_WAIT(2);
        __syncthreads();
        const uint32_t As = sb + (i % 3) * STAGE_H;
        const uint32_t Bs = As + 16384;
#pragma unroll
        for (int ks = 0; ks < 4; ks++) {
            uint32_t a[4][4], b[2][4];
#pragma unroll
            for (int mt = 0; mt < 4; mt++) {
                int row = wm * 64 + mt * 16 + (lane & 15);
                int ch  = ks * 2 + (lane >> 4);
                ldsm_x4(a[mt][0], a[mt][1], a[mt][2], a[mt][3],
                        As + row * 128 + ((ch ^ (row & 7)) << 4));
            }
#pragma unroll
            for (int p = 0; p < 2; p++) {
                int row = wn * 32 + p * 16 + ((lane >> 4) << 3) + (lane & 7);
                int ch  = ks * 2 + ((lane >> 3) & 1);
                ldsm_x4(b[p][0], b[p][1], b[p][2], b[p][3],
                        Bs + row * 128 + ((ch ^ (row & 7)) << 4));
            }
#pragma unroll
            for (int mt = 0; mt < 4; mt++)
#pragma unroll
                for (int nt = 0; nt < 4; nt++)
                    mma_f16(acc[mt][nt], a[mt], &b[nt >> 1][(nt & 1) * 2]);
        }
        __syncthreads();
        if (i + 3 < 32) issue1(i + 3);
        else CP_COMMIT();
    }
    CP_WAIT(0);

    {
        const float scale = rsqrtf((float)SSZ);
        const int r = lane >> 2;
        const int c = lane & 3;
#pragma unroll
        for (int mt = 0; mt < 4; mt++) {
            int row0 = wm * 64 + mt * 16 + r;
            int row1 = row0 + 8;
#pragma unroll
            for (int nt = 0; nt < 4; nt++) {
                int col = wn * 32 + nt * 8 + c * 2;
                scores[row0 * 128 + col]     = (col     <= row0) ? acc[mt][nt][0] * scale : -1e30f;
                scores[row0 * 128 + col + 1] = (col + 1 <= row0) ? acc[mt][nt][1] * scale : -1e30f;
                scores[row1 * 128 + col]     = (col     <= row1) ? acc[mt][nt][2] * scale : -1e30f;
                scores[row1 * 128 + col + 1] = (col + 1 <= row1) ? acc[mt][nt][3] * scale : -1e30f;
            }
        }
    }
    __syncthreads();

#pragma unroll 4
    for (int rr = 0; rr < 16; rr++) {
        int row = wid * 16 + rr;
        float v0 = scores[row * 128 + lane];
        float v1 = scores[row * 128 + lane + 32];
        float v2 = scores[row * 128 + lane + 64];
        float v3 = scores[row * 128 + lane + 96];
        float mx = fmaxf(fmaxf(v0, v1), fmaxf(v2, v3));
#pragma unroll
        for (int o = 16; o > 0; o >>= 1)
            mx = fmaxf(mx, __shfl_xor_sync(0xFFFFFFFFu, mx, o));
        float e0 = __expf(v0 - mx), e1 = __expf(v1 - mx);
        float e2 = __expf(v2 - mx), e3 = __expf(v3 - mx);
        float sm = e0 + e1 + e2 + e3;
#pragma unroll
        for (int o = 16; o > 0; o >>= 1)
            sm += __shfl_xor_sync(0xFFFFFFFFu, sm, o);
        float inv = 1.0f / sm;
        float ev[4] = {e0, e1, e2, e3};
#pragma unroll
        for (int j = 0; j < 4; j++) {
            int col = lane + 32 * j;
            int hidx = row * 128 + ((((col >> 3) ^ (row & 7))) << 3) + (col & 7);
            Pp[hidx] = __float2half_rn(ev[j] * inv);
        }
    }

    auto issueV = [&](int nc) {
        const uint32_t Vb = sb + (nc & 1) * 32768;
        const int n0 = nc * 128;
#pragma unroll
        for (int i = 0; i < 8; i++) {
            int idx = i * 256 + t;
            int e = idx >> 4;
            int c = idx & 15;
            cp16(Vb + (uint32_t)(e * 256 + ((c ^ (e & 7)) << 4)),
                 v + (size_t)e * SSZ + n0 + c * 8);
        }
        CP_COMMIT();
    };
    issueV(0);

    __half* OTp = (__half*)(smem + OFF_SC);

    for (int nc = 0; nc < 16; nc++) {
        if (nc + 1 < 16) { issueV(nc + 1); CP_WAIT(1); }
        else             { CP_WAIT(0); }
        __syncthreads();

        const uint32_t Vb = sb + (nc & 1) * 32768;
#pragma unroll
        for (int mt = 0; mt < 4; mt++)
#pragma unroll
            for (int nt = 0; nt < 4; nt++)
#pragma unroll
                for (int x = 0; x < 4; x++) acc[mt][nt][x] = 0.0f;

#pragma unroll
        for (int ks = 0; ks < 8; ks++) {
            uint32_t a[4][4], b[2][4];
#pragma unroll
            for (int mt = 0; mt < 4; mt++) {
                int row = wm * 64 + mt * 16 + (lane & 15);
                int ch  = ks * 2 + (lane >> 4);
                ldsm_x4(a[mt][0], a[mt][1], a[mt][2], a[mt][3],
                        Pb + row * 256 + ((ch ^ (row & 7)) << 4));
            }
#pragma unroll
            for (int p = 0; p < 2; p++) {
                int nb  = wn * 32 + p * 16;
                int grp = lane >> 3;
                int li  = lane & 7;
                int e   = ks * 16 + ((grp & 1) << 3) + li;
                int ncol = nb + ((grp >> 1) << 3);
                ldsm_x4_t(b[p][0], b[p][1], b[p][2], b[p][3],
                          Vb + e * 256 + (((ncol >> 3) ^ (e & 7)) << 4));
            }
#pragma unroll
            for (int mt = 0; mt < 4; mt++)
#pragma unroll
                for (int nt = 0; nt < 4; nt++)
                    mma_f16(acc[mt][nt], a[mt], &b[nt >> 1][(nt & 1) * 2]);
        }

        {
            const int r = lane >> 2;
            const int c = lane & 3;
#pragma unroll
            for (int mt = 0; mt < 4; mt++) {
                int row0 = wm * 64 + mt * 16 + r;
#pragma unroll
                for (int nt = 0; nt < 4; nt++) {
                    int col = wn * 32 + nt * 8 + c * 2;
                    OTp[col * 128 + row0]           = __float2half_rn(acc[mt][nt][0]);
                    OTp[(col + 1) * 128 + row0]     = __float2half_rn(acc[mt][nt][1]);
                    OTp[col * 128 + row0 + 8]       = __float2half_rn(acc[mt][nt][2]);
                    OTp[(col + 1) * 128 + row0 + 8] = __float2half_rn(acc[mt][nt][3]);
                }
            }
        }
        __syncthreads();

        {
            int s  = t >> 1;
            int dp = (t & 1) * 64;
            const uint4* src = (const uint4*)(OTp + s * 128 + dp);
            uint4* dst = (uint4*)(oT + (size_t)(nc * 128 + s) * CH + dp);
#pragma unroll
            for (int u = 0; u < 8; u++) dst[u] = src[u];
        }
        __syncthreads();
    }
}

// ===========================================================================
// Launch
// ===========================================================================
extern "C" void kernel_launch(void* const* d_in, const int* in_sizes, int n_in,
                              void* d_out, int out_size)
{
    const float* hs = (const float*)d_in[0];
    const float* Wq = (const float*)d_in[1];
    const float* bq = (const float*)d_in[2];
    const float* Wk = (const float*)d_in[3];
    const float* bk = (const float*)d_in[4];
    const float* Wv = (const float*)d_in[5];
    const float* bv = (const float*)d_in[6];
    const float* Wo = (const float*)d_in[7];
    const float* bo = (const float*)d_in[8];

    float *kfb, *vfb;
    __half *qh, *kh, *vh, *atbufh, *xth, *wh;
    cudaGetSymbolAddress((void**)&qh,     g_qh);
    cudaGetSymbolAddress((void**)&kh,     g_kh);
    cudaGetSymbolAddress((void**)&vh,     g_vh);
    cudaGetSymbolAddress((void**)&atbufh, g_attnTh);
    cudaGetSymbolAddress((void**)&xth,    g_xth);
    cudaGetSymbolAddress((void**)&wh,     g_wh);
    cudaGetSymbolAddress((void**)&kfb,    g_kfb);
    cudaGetSymbolAddress((void**)&vfb,    g_vfb);

    float* out = (float*)d_out;
    float* kout;
    float* vout;
    if ((long long)out_size >= 3LL * BHS) {
        kout = out + (size_t)BHS;
        vout = out + 2 * (size_t)BHS;
    } else {
        kout = kfb;
        vout = vfb;
    }

    // ---- Prep ----
    round_half4_kernel<<<dim3(WSZ / (256 * 8), 4), 256>>>(Wq, Wk, Wv, Wo, wh);
    transpose_half_kernel<<<dim3(SSZ / 32, CH / 32, BB), 256>>>(hs, xth);

    // ---- Fused Q/K/V projections ----
    cudaFuncSetAttribute(gemm_qkv,
                         cudaFuncAttributeMaxDynamicSharedMemorySize, SMEM_G);
    cudaFuncSetAttribute(gemm_one,
                         cudaFuncAttributeMaxDynamicSharedMemorySize, SMEM_G);
    dim3 blk(128, 1, 1);
    gemm_qkv<<<dim3(SSZ / 128, 96, BB), blk, SMEM_G>>>(
        wh, xth, bq, bk, bv, qh, kout, kh, vout, vh);

    // ---- Tensor-core attention ----
    cudaFuncSetAttribute(attn_tc,
                         cudaFuncAttributeMaxDynamicSharedMemorySize, ATTN_SMEM);
    attn_tc<<<BB * NH, 256, ATTN_SMEM>>>(qh, kh, vh, atbufh);

    // ---- Output projection ----
    gemm_one<<<dim3(SSZ / 128, CH / 128, BB), blk, SMEM_G>>>(
        wh + 3 * (size_t)WSZ, atbufh, bo, out);
}

// round 8
// speedup vs baseline: 1.1466x; 1.0200x over previous
#include <cuda_runtime.h>
#include <cuda_fp16.h>
#include <math.h>
#include <stdint.h>

// Problem constants
#define BB 4
#define CH 4096     // HID
#define SSZ 2048    // S
#define NH 32       // heads
#define HD 128      // head dim

#define BHS 33554432   // BB*CH*SSZ elements
#define WSZ 16777216   // CH*CH elements

// Scratch (allocation-free rule: __device__ globals)
__device__ __half g_qh[BHS];      // Q half [b][ch][s]
__device__ __half g_kh[BHS];      // K half [b][ch][s]
__device__ __half g_vh[BHS];      // V half [b][ch][s]
__device__ __half g_attnTh[BHS];  // attention out, transposed half [b][s][ch]
__device__ __half g_xth[BHS];     // hidden transposed half [b][s][ch]
__device__ __half g_wh[4 * WSZ];  // half Wq,Wk,Wv,Wo (row-major, K-contig)
__device__ float  g_kfb[BHS];     // fallback K dest
__device__ float  g_vfb[BHS];     // fallback V dest

// ===========================================================================
// Helpers
// ===========================================================================
__device__ __forceinline__ uint32_t smem_u32(const void* p) {
    uint32_t a;
    asm("{ .reg .u64 t; cvta.to.shared.u64 t, %1; cvt.u32.u64 %0, t; }"
        : "=r"(a) : "l"(p));
    return a;
}

__device__ __forceinline__ void cp16(uint32_t dst, const void* src) {
    asm volatile("cp.async.cg.shared.global [%0], [%1], 16;"
                 :: "r"(dst), "l"(src) : "memory");
}
#define CP_COMMIT() asm volatile("cp.async.commit_group;" ::: "memory")
#define CP_WAIT(n)  asm volatile("cp.async.wait_group %0;" :: "n"(n) : "memory")

__device__ __forceinline__ void ldsm_x4(uint32_t& r0, uint32_t& r1,
                                        uint32_t& r2, uint32_t& r3, uint32_t addr) {
    asm volatile("ldmatrix.sync.aligned.m8n8.x4.shared.b16 {%0,%1,%2,%3}, [%4];"
                 : "=r"(r0), "=r"(r1), "=r"(r2), "=r"(r3) : "r"(addr));
}

__device__ __forceinline__ void ldsm_x4_t(uint32_t& r0, uint32_t& r1,
                                          uint32_t& r2, uint32_t& r3, uint32_t addr) {
    asm volatile("ldmatrix.sync.aligned.m8n8.x4.trans.shared.b16 {%0,%1,%2,%3}, [%4];"
                 : "=r"(r0), "=r"(r1), "=r"(r2), "=r"(r3) : "r"(addr));
}

// mma m16n8k16 f16 inputs, f32 accumulate
__device__ __forceinline__ void mma_f16(float* d, const uint32_t* a, const uint32_t* b) {
    asm volatile(
        "mma.sync.aligned.m16n8k16.row.col.f32.f16.f16.f32 "
        "{%0,%1,%2,%3}, {%4,%5,%6,%7}, {%8,%9}, {%0,%1,%2,%3};"
        : "+f"(d[0]), "+f"(d[1]), "+f"(d[2]), "+f"(d[3])
        : "r"(a[0]), "r"(a[1]), "r"(a[2]), "r"(a[3]), "r"(b[0]), "r"(b[1]));
}

// ===========================================================================
// Prep kernels
// ===========================================================================
__global__ void round_half4_kernel(
    const float* __restrict__ W0, const float* __restrict__ W1,
    const float* __restrict__ W2, const float* __restrict__ W3,
    __half* __restrict__ Wh)
{
    const float* W = (blockIdx.y == 0) ? W0 : (blockIdx.y == 1) ? W1
                   : (blockIdx.y == 2) ? W2 : W3;
    __half* dst = Wh + (size_t)blockIdx.y * WSZ;
    size_t i = ((size_t)blockIdx.x * 256 + threadIdx.x) * 8;
    float4 v0 = *(const float4*)(W + i);
    float4 v1 = *(const float4*)(W + i + 4);
    __half2 h0 = __floats2half2_rn(v0.x, v0.y);
    __half2 h1 = __floats2half2_rn(v0.z, v0.w);
    __half2 h2 = __floats2half2_rn(v1.x, v1.y);
    __half2 h3 = __floats2half2_rn(v1.z, v1.w);
    uint4 o;
    o.x = *(uint32_t*)&h0; o.y = *(uint32_t*)&h1;
    o.z = *(uint32_t*)&h2; o.w = *(uint32_t*)&h3;
    *(uint4*)(dst + i) = o;
}

// X [b][ch][s] fp32 -> Xt [b][s][ch] half
__global__ void transpose_half_kernel(const float* __restrict__ X, __half* __restrict__ Xt) {
    __shared__ float tile[32][33];
    const int b  = blockIdx.z;
    const int k0 = blockIdx.y * 32;
    const int n0 = blockIdx.x * 32;
    const float* Xb  = X  + (size_t)b * CH * SSZ;
    __half*      Xtb = Xt + (size_t)b * SSZ * CH;
    const int tx = threadIdx.x & 31;
    const int ty = threadIdx.x >> 5;
#pragma unroll
    for (int i = 0; i < 4; i++)
        tile[ty + i * 8][tx] = Xb[(size_t)(k0 + ty + i * 8) * SSZ + n0 + tx];
    __syncthreads();
#pragma unroll
    for (int i = 0; i < 4; i++)
        Xtb[(size_t)(n0 + ty + i * 8) * CH + k0 + tx] =
            __float2half_rn(tile[tx][ty + i * 8]);
}

// ===========================================================================
// Persistent fp16 tensor-core GEMM:
//   mode 0 (QKV): 6144 tiles; tile idx -> (x:16, y:96, z:4), widx = y>>5.
//   mode 1 (O)  : 2048 tiles; tile idx -> (x:16, y:32, z:4).
// CTA tile 128x128, K-chunk 64, 3-stage cp.async, 4 warps (2Mx2N), warp 64x64.
// Issue cursor runs 3 chunks ahead of compute ACROSS tile boundaries, so the
// pipeline never drains at a tile switch; epilogue overlaps next tile's loads.
// ===========================================================================
#define STAGE_B 32768
#define SMEM_G  (3 * STAGE_B)   // 98304

struct TileCtx {
    const __half* A;     // weight strip base (m0 folded)
    const __half* B;     // activation strip base (n0 folded)
    const float*  bias;  // + m0
    float*  Yf;          // + z + m0*SSZ + n0 (or null)
    __half* Yh;          // + z + m0*SSZ + n0 (or null)
};

__global__ __launch_bounds__(128, 2) void gemm_persist(
    const __half* __restrict__ Wbase, const __half* __restrict__ Bbase,
    const float* __restrict__ b0, const float* __restrict__ b1,
    const float* __restrict__ b2,
    __half* __restrict__ H0, float* __restrict__ F1, __half* __restrict__ H1,
    float* __restrict__ F2, __half* __restrict__ H2,
    int mode, int ntiles)
{
    extern __shared__ char smem[];
    const uint32_t sb = smem_u32(smem);
    const int t    = threadIdx.x;
    const int lane = t & 31;
    const int wid  = t >> 5;     // 0..3
    const int wm   = wid >> 1;   // 0..1
    const int wn   = wid & 1;    // 0..1
    const int lr = t >> 3;       // 0..15
    const int lc = t & 7;

    auto decode = [&](int idx, TileCtx& c) {
        int x  = idx & 15;
        int n0 = x << 7;
        if (mode == 0) {
            int r = idx >> 4;
            int y = r % 96;
            int z = r / 96;
            int widx = y >> 5;
            int m0 = (y & 31) << 7;
            c.A = Wbase + (size_t)widx * WSZ + (size_t)m0 * CH;
            c.B = Bbase + (size_t)z * SSZ * CH + (size_t)n0 * CH;
            c.bias = ((widx == 0) ? b0 : (widx == 1) ? b1 : b2) + m0;
            size_t o = (size_t)z * CH * SSZ + (size_t)m0 * SSZ + n0;
            c.Yf = (widx == 0) ? (float*)0 : (((widx == 1) ? F1 : F2) + o);
            c.Yh = ((widx == 0) ? H0 : (widx == 1) ? H1 : H2) + o;
        } else {
            int y = (idx >> 4) & 31;
            int z = idx >> 9;
            int m0 = y << 7;
            c.A = Wbase + (size_t)m0 * CH;
            c.B = Bbase + (size_t)z * SSZ * CH + (size_t)n0 * CH;
            c.bias = b0 + m0;
            c.Yf = F1 + (size_t)z * CH * SSZ + (size_t)m0 * SSZ + n0;
            c.Yh = (__half*)0;
        }
    };

    // ---- issue cursor (3 chunks ahead of compute, crosses tile boundaries)
    TileCtx ictx;
    int itile  = blockIdx.x;
    int ichunk = 0;
    int istage = 0;
    bool ivalid = (itile < ntiles);
    if (ivalid) decode(itile, ictx);

    auto issue = [&]() {
        if (ivalid) {
            const int k0 = ichunk * 64;
            const uint32_t As = sb + istage * STAGE_B;
            const uint32_t Bs = As + 16384;
#pragma unroll
            for (int it = 0; it < 8; it++) {
                int m = it * 16 + lr;
                cp16(As + (uint32_t)(m * 128 + ((lc ^ (m & 7)) << 4)),
                     ictx.A + (size_t)m * CH + k0 + lc * 8);
            }
#pragma unroll
            for (int it = 0; it < 8; it++) {
                int n = it * 16 + lr;
                cp16(Bs + (uint32_t)(n * 128 + ((lc ^ (n & 7)) << 4)),
                     ictx.B + (size_t)n * CH + k0 + lc * 8);
            }
            istage = (istage == 2) ? 0 : istage + 1;
            if (++ichunk == 64) {
                ichunk = 0;
                itile += gridDim.x;
                ivalid = (itile < ntiles);
                if (ivalid) decode(itile, ictx);
            }
        }
        CP_COMMIT();
    };

    issue(); issue(); issue();
    int cstage = 0;

    for (int tt = blockIdx.x; tt < ntiles; tt += gridDim.x) {
        TileCtx cc;
        decode(tt, cc);

        float acc[4][8][4];
#pragma unroll
        for (int mt = 0; mt < 4; mt++)
#pragma unroll
            for (int nt = 0; nt < 8; nt++)
#pragma unroll
                for (int x = 0; x < 4; x++) acc[mt][nt][x] = 0.0f;

        for (int i = 0; i < 64; i++) {
            CP_WAIT(2);
            __syncthreads();
            const uint32_t As = sb + cstage * STAGE_B;
            const uint32_t Bs = As + 16384;
#pragma unroll
            for (int ks = 0; ks < 4; ks++) {
                uint32_t a[4][4], b[4][4];
#pragma unroll
                for (int mt = 0; mt < 4; mt++) {
                    int row = wm * 64 + mt * 16 + (lane & 15);
                    int ch  = ks * 2 + (lane >> 4);
                    ldsm_x4(a[mt][0], a[mt][1], a[mt][2], a[mt][3],
                            As + row * 128 + ((ch ^ (row & 7)) << 4));
                }
#pragma unroll
                for (int p = 0; p < 4; p++) {
                    int row = wn * 64 + p * 16 + ((lane >> 4) << 3) + (lane & 7);
                    int ch  = ks * 2 + ((lane >> 3) & 1);
                    ldsm_x4(b[p][0], b[p][1], b[p][2], b[p][3],
                            Bs + row * 128 + ((ch ^ (row & 7)) << 4));
                }
#pragma unroll
                for (int mt = 0; mt < 4; mt++)
#pragma unroll
                    for (int nt = 0; nt < 8; nt++)
                        mma_f16(acc[mt][nt], a[mt], &b[nt >> 1][(nt & 1) * 2]);
            }
            __syncthreads();
            cstage = (cstage == 2) ? 0 : cstage + 1;
            issue();
        }

        // Epilogue: direct reg->global (no smem); overlaps next tile's cp.async
        const int r  = lane >> 2;
        const int c4 = lane & 3;
#pragma unroll
        for (int mt = 0; mt < 4; mt++) {
            int rr = wm * 64 + mt * 16 + r;
            float bv0 = cc.bias[rr];
            float bv1 = cc.bias[rr + 8];
#pragma unroll
            for (int nt = 0; nt < 8; nt++) {
                int col = wn * 64 + nt * 8 + c4 * 2;
                float f00 = acc[mt][nt][0] + bv0, f01 = acc[mt][nt][1] + bv0;
                float f10 = acc[mt][nt][2] + bv1, f11 = acc[mt][nt][3] + bv1;
                if (cc.Yf) {
                    *(float2*)&cc.Yf[(size_t)rr * SSZ + col]       = make_float2(f00, f01);
                    *(float2*)&cc.Yf[(size_t)(rr + 8) * SSZ + col] = make_float2(f10, f11);
                }
                if (cc.Yh) {
                    __half2 h0 = __floats2half2_rn(f00, f01);
                    __half2 h1 = __floats2half2_rn(f10, f11);
                    *(__half2*)&cc.Yh[(size_t)rr * SSZ + col]       = h0;
                    *(__half2*)&cc.Yh[(size_t)(rr + 8) * SSZ + col] = h1;
                }
            }
        }
    }
}

// ===========================================================================
// Tensor-core attention, 1 CTA per (b,h), 256 threads. (unchanged from R5)
// ===========================================================================
#define STAGE_H 32768
#define ATTN_SMEM 196608
#define OFF_SC 98304
#define OFF_P  163840

__global__ __launch_bounds__(256, 1) void attn_tc(
    const __half* __restrict__ Qh, const __half* __restrict__ Kh,
    const __half* __restrict__ Vh, __half* __restrict__ OT)
{
    extern __shared__ char smem[];
    const uint32_t sb = smem_u32(smem);
    float*  scores = (float*)(smem + OFF_SC);
    __half* Pp     = (__half*)(smem + OFF_P);
    const uint32_t Pb = sb + OFF_P;

    const int bh = blockIdx.x;
    const int b_ = bh >> 5, h_ = bh & 31;
    const size_t hb = ((size_t)b_ * CH + (size_t)h_ * HD) * SSZ;
    const __half* q = Qh + hb;
    const __half* k = Kh + hb;
    const __half* v = Vh + hb;
    __half* oT = OT + (size_t)b_ * SSZ * CH + h_ * HD;

    const int t    = threadIdx.x;
    const int lane = t & 31;
    const int wid  = t >> 5;
    const int wm   = wid >> 2;
    const int wn   = wid & 3;
    const int lr = t >> 3;
    const int lc = t & 7;

    float acc[4][4][4];
#pragma unroll
    for (int mt = 0; mt < 4; mt++)
#pragma unroll
        for (int nt = 0; nt < 4; nt++)
#pragma unroll
            for (int x = 0; x < 4; x++) acc[mt][nt][x] = 0.0f;

    auto issue1 = [&](int chunk) {
        const int stage = chunk % 3;
        const int k0 = chunk * 64;
        const uint32_t As = sb + stage * STAGE_H;
        const uint32_t Bs = As + 16384;
#pragma unroll
        for (int it = 0; it < 4; it++) {
            int m = it * 32 + lr;
            uint32_t sw = (uint32_t)(m * 128 + ((lc ^ (m & 7)) << 4));
            cp16(As + sw, q + (size_t)m * SSZ + k0 + lc * 8);
            cp16(Bs + sw, k + (size_t)m * SSZ + k0 + lc * 8);
        }
        CP_COMMIT();
    };
    issue1(0); issue1(1); issue1(2);

    for (int i = 0; i < 32; i++) {
        CP_WAIT(2);
        __syncthreads();
        const uint32_t As = sb + (i % 3) * STAGE_H;
        const uint32_t Bs = As + 16384;
#pragma unroll
        for (int ks = 0; ks < 4; ks++) {
            uint32_t a[4][4], b[2][4];
#pragma unroll
            for (int mt = 0; mt < 4; mt++) {
                int row = wm * 64 + mt * 16 + (lane & 15);
                int ch  = ks * 2 + (lane >> 4);
                ldsm_x4(a[mt][0], a[mt][1], a[mt][2], a[mt][3],
                        As + row * 128 + ((ch ^ (row & 7)) << 4));
            }
#pragma unroll
            for (int p = 0; p < 2; p++) {
                int row = wn * 32 + p * 16 + ((lane >> 4) << 3) + (lane & 7);
                int ch  = ks * 2 + ((lane >> 3) & 1);
                ldsm_x4(b[p][0], b[p][1], b[p][2], b[p][3],
                        Bs + row * 128 + ((ch ^ (row & 7)) << 4));
            }
#pragma unroll
            for (int mt = 0; mt < 4; mt++)
#pragma unroll
                for (int nt = 0; nt < 4; nt++)
                    mma_f16(acc[mt][nt], a[mt], &b[nt >> 1][(nt & 1) * 2]);
        }
        __syncthreads();
        if (i + 3 < 32) issue1(i + 3);
        else CP_COMMIT();
    }
    CP_WAIT(0);

    {
        const float scale = rsqrtf((float)SSZ);
        const int r = lane >> 2;
        const int c = lane & 3;
#pragma unroll
        for (int mt = 0; mt < 4; mt++) {
            int row0 = wm * 64 + mt * 16 + r;
            int row1 = row0 + 8;
#pragma unroll
            for (int nt = 0; nt < 4; nt++) {
                int col = wn * 32 + nt * 8 + c * 2;
                scores[row0 * 128 + col]     = (col     <= row0) ? acc[mt][nt][0] * scale : -1e30f;
                scores[row0 * 128 + col + 1] = (col + 1 <= row0) ? acc[mt][nt][1] * scale : -1e30f;
                scores[row1 * 128 + col]     = (col     <= row1) ? acc[mt][nt][2] * scale : -1e30f;
                scores[row1 * 128 + col + 1] = (col + 1 <= row1) ? acc[mt][nt][3] * scale : -1e30f;
            }
        }
    }
    __syncthreads();

#pragma unroll 4
    for (int rr = 0; rr < 16; rr++) {
        int row = wid * 16 + rr;
        float v0 = scores[row * 128 + lane];
        float v1 = scores[row * 128 + lane + 32];
        float v2 = scores[row * 128 + lane + 64];
        float v3 = scores[row * 128 + lane + 96];
        float mx = fmaxf(fmaxf(v0, v1), fmaxf(v2, v3));
#pragma unroll
        for (int o = 16; o > 0; o >>= 1)
            mx = fmaxf(mx, __shfl_xor_sync(0xFFFFFFFFu, mx, o));
        float e0 = __expf(v0 - mx), e1 = __expf(v1 - mx);
        float e2 = __expf(v2 - mx), e3 = __expf(v3 - mx);
        float sm = e0 + e1 + e2 + e3;
#pragma unroll
        for (int o = 16; o > 0; o >>= 1)
            sm += __shfl_xor_sync(0xFFFFFFFFu, sm, o);
        float inv = 1.0f / sm;
        float ev[4] = {e0, e1, e2, e3};
#pragma unroll
        for (int j = 0; j < 4; j++) {
            int col = lane + 32 * j;
            int hidx = row * 128 + ((((col >> 3) ^ (row & 7))) << 3) + (col & 7);
            Pp[hidx] = __float2half_rn(ev[j] * inv);
        }
    }

    auto issueV = [&](int nc) {
        const uint32_t Vb = sb + (nc & 1) * 32768;
        const int n0 = nc * 128;
#pragma unroll
        for (int i = 0; i < 8; i++) {
            int idx = i * 256 + t;
            int e = idx >> 4;
            int c = idx & 15;
            cp16(Vb + (uint32_t)(e * 256 + ((c ^ (e & 7)) << 4)),
                 v + (size_t)e * SSZ + n0 + c * 8);
        }
        CP_COMMIT();
    };
    issueV(0);

    __half* OTp = (__half*)(smem + OFF_SC);

    for (int nc = 0; nc < 16; nc++) {
        if (nc + 1 < 16) { issueV(nc + 1); CP_WAIT(1); }
        else             { CP_WAIT(0); }
        __syncthreads();

        const uint32_t Vb = sb + (nc & 1) * 32768;
#pragma unroll
        for (int mt = 0; mt < 4; mt++)
#pragma unroll
            for (int nt = 0; nt < 4; nt++)
#pragma unroll
                for (int x = 0; x < 4; x++) acc[mt][nt][x] = 0.0f;

#pragma unroll
        for (int ks = 0; ks < 8; ks++) {
            uint32_t a[4][4], b[2][4];
#pragma unroll
            for (int mt = 0; mt < 4; mt++) {
                int row = wm * 64 + mt * 16 + (lane & 15);
                int ch  = ks * 2 + (lane >> 4);
                ldsm_x4(a[mt][0], a[mt][1], a[mt][2], a[mt][3],
                        Pb + row * 256 + ((ch ^ (row & 7)) << 4));
            }
#pragma unroll
            for (int p = 0; p < 2; p++) {
                int nb  = wn * 32 + p * 16;
                int grp = lane >> 3;
                int li  = lane & 7;
                int e   = ks * 16 + ((grp & 1) << 3) + li;
                int ncol = nb + ((grp >> 1) << 3);
                ldsm_x4_t(b[p][0], b[p][1], b[p][2], b[p][3],
                          Vb + e * 256 + (((ncol >> 3) ^ (e & 7)) << 4));
            }
#pragma unroll
            for (int mt = 0; mt < 4; mt++)
#pragma unroll
                for (int nt = 0; nt < 4; nt++)
                    mma_f16(acc[mt][nt], a[mt], &b[nt >> 1][(nt & 1) * 2]);
        }

        {
            const int r = lane >> 2;
            const int c = lane & 3;
#pragma unroll
            for (int mt = 0; mt < 4; mt++) {
                int row0 = wm * 64 + mt * 16 + r;
#pragma unroll
                for (int nt = 0; nt < 4; nt++) {
                    int col = wn * 32 + nt * 8 + c * 2;
                    OTp[col * 128 + row0]           = __float2half_rn(acc[mt][nt][0]);
                    OTp[(col + 1) * 128 + row0]     = __float2half_rn(acc[mt][nt][1]);
                    OTp[col * 128 + row0 + 8]       = __float2half_rn(acc[mt][nt][2]);
                    OTp[(col + 1) * 128 + row0 + 8] = __float2half_rn(acc[mt][nt][3]);
                }
            }
        }
        __syncthreads();

        {
            int s  = t >> 1;
            int dp = (t & 1) * 64;
            const uint4* src = (const uint4*)(OTp + s * 128 + dp);
            uint4* dst = (uint4*)(oT + (size_t)(nc * 128 + s) * CH + dp);
#pragma unroll
            for (int u = 0; u < 8; u++) dst[u] = src[u];
        }
        __syncthreads();
    }
}

// ===========================================================================
// Launch
// ===========================================================================
extern "C" void kernel_launch(void* const* d_in, const int* in_sizes, int n_in,
                              void* d_out, int out_size)
{
    const float* hs = (const float*)d_in[0];
    const float* Wq = (const float*)d_in[1];
    const float* bq = (const float*)d_in[2];
    const float* Wk = (const float*)d_in[3];
    const float* bk = (const float*)d_in[4];
    const float* Wv = (const float*)d_in[5];
    const float* bv = (const float*)d_in[6];
    const float* Wo = (const float*)d_in[7];
    const float* bo = (const float*)d_in[8];

    float *kfb, *vfb;
    __half *qh, *kh, *vh, *atbufh, *xth, *wh;
    cudaGetSymbolAddress((void**)&qh,     g_qh);
    cudaGetSymbolAddress((void**)&kh,     g_kh);
    cudaGetSymbolAddress((void**)&vh,     g_vh);
    cudaGetSymbolAddress((void**)&atbufh, g_attnTh);
    cudaGetSymbolAddress((void**)&xth,    g_xth);
    cudaGetSymbolAddress((void**)&wh,     g_wh);
    cudaGetSymbolAddress((void**)&kfb,    g_kfb);
    cudaGetSymbolAddress((void**)&vfb,    g_vfb);

    float* out = (float*)d_out;
    float* kout;
    float* vout;
    if ((long long)out_size >= 3LL * BHS) {
        kout = out + (size_t)BHS;
        vout = out + 2 * (size_t)BHS;
    } else {
        kout = kfb;
        vout = vfb;
    }

    int sms = 148;
    cudaDeviceGetAttribute(&sms, cudaDevAttrMultiProcessorCount, 0);
    const int pgrid = 2 * sms;   // exactly-resident persistent grid

    // ---- Prep ----
    round_half4_kernel<<<dim3(WSZ / (256 * 8), 4), 256>>>(Wq, Wk, Wv, Wo, wh);
    transpose_half_kernel<<<dim3(SSZ / 32, CH / 32, BB), 256>>>(hs, xth);

    // ---- Persistent Q/K/V projections (6144 tiles) ----
    cudaFuncSetAttribute(gemm_persist,
                         cudaFuncAttributeMaxDynamicSharedMemorySize, SMEM_G);
    gemm_persist<<<pgrid, 128, SMEM_G>>>(
        wh, xth, bq, bk, bv, qh, kout, kh, vout, vh, 0, 6144);

    // ---- Tensor-core attention ----
    cudaFuncSetAttribute(attn_tc,
                         cudaFuncAttributeMaxDynamicSharedMemorySize, ATTN_SMEM);
    attn_tc<<<BB * NH, 256, ATTN_SMEM>>>(qh, kh, vh, atbufh);

    // ---- Persistent output projection (2048 tiles) ----
    gemm_persist<<<pgrid, 128, SMEM_G>>>(
        wh + 3 * (size_t)WSZ, atbufh, bo, (const float*)0, (const float*)0,
        (__half*)0, out, (__half*)0, (float*)0, (__half*)0, 1, 2048);
}

// round 9
// speedup vs baseline: 1.1531x; 1.0057x over previous
#include <cuda_runtime.h>
#include <cuda_fp16.h>
#include <math.h>
#include <stdint.h>

// Problem constants
#define BB 4
#define CH 4096     // HID
#define SSZ 2048    // S
#define NH 32       // heads
#define HD 128      // head dim

#define BHS 33554432   // BB*CH*SSZ elements
#define WSZ 16777216   // CH*CH elements

// Scratch (allocation-free rule: __device__ globals)
__device__ __half g_qh[BHS];      // Q half [b][ch][s]
__device__ __half g_kh[BHS];      // K half [b][ch][s]
__device__ __half g_vh[BHS];      // V half [b][ch][s]
__device__ __half g_attnTh[BHS];  // attention out, transposed half [b][s][ch]
__device__ __half g_xth[BHS];     // hidden transposed half [b][s][ch]
__device__ __half g_wh[4 * WSZ];  // half Wq,Wk,Wv,Wo (row-major, K-contig)
__device__ float  g_kfb[BHS];     // fallback K dest
__device__ float  g_vfb[BHS];     // fallback V dest

// ===========================================================================
// Helpers
// ===========================================================================
__device__ __forceinline__ uint32_t smem_u32(const void* p) {
    uint32_t a;
    asm("{ .reg .u64 t; cvta.to.shared.u64 t, %1; cvt.u32.u64 %0, t; }"
        : "=r"(a) : "l"(p));
    return a;
}

__device__ __forceinline__ void cp16(uint32_t dst, const void* src) {
    asm volatile("cp.async.cg.shared.global [%0], [%1], 16;"
                 :: "r"(dst), "l"(src) : "memory");
}
#define CP_COMMIT() asm volatile("cp.async.commit_group;" ::: "memory")
#define CP_WAIT(n)  asm volatile("cp.async.wait_group %0;" :: "n"(n) : "memory")

__device__ __forceinline__ void ldsm_x4(uint32_t& r0, uint32_t& r1,
                                        uint32_t& r2, uint32_t& r3, uint32_t addr) {
    asm volatile("ldmatrix.sync.aligned.m8n8.x4.shared.b16 {%0,%1,%2,%3}, [%4];"
                 : "=r"(r0), "=r"(r1), "=r"(r2), "=r"(r3) : "r"(addr));
}

__device__ __forceinline__ void ldsm_x4_t(uint32_t& r0, uint32_t& r1,
                                          uint32_t& r2, uint32_t& r3, uint32_t addr) {
    asm volatile("ldmatrix.sync.aligned.m8n8.x4.trans.shared.b16 {%0,%1,%2,%3}, [%4];"
                 : "=r"(r0), "=r"(r1), "=r"(r2), "=r"(r3) : "r"(addr));
}

// mma m16n8k16 f16 inputs, f32 accumulate
__device__ __forceinline__ void mma_f16(float* d, const uint32_t* a, const uint32_t* b) {
    asm volatile(
        "mma.sync.aligned.m16n8k16.row.col.f32.f16.f16.f32 "
        "{%0,%1,%2,%3}, {%4,%5,%6,%7}, {%8,%9}, {%0,%1,%2,%3};"
        : "+f"(d[0]), "+f"(d[1]), "+f"(d[2]), "+f"(d[3])
        : "r"(a[0]), "r"(a[1]), "r"(a[2]), "r"(a[3]), "r"(b[0]), "r"(b[1]));
}

// ===========================================================================
// Prep kernels
// ===========================================================================
__global__ void round_half4_kernel(
    const float* __restrict__ W0, const float* __restrict__ W1,
    const float* __restrict__ W2, const float* __restrict__ W3,
    __half* __restrict__ Wh)
{
    const float* W = (blockIdx.y == 0) ? W0 : (blockIdx.y == 1) ? W1
                   : (blockIdx.y == 2) ? W2 : W3;
    __half* dst = Wh + (size_t)blockIdx.y * WSZ;
    size_t i = ((size_t)blockIdx.x * 256 + threadIdx.x) * 8;
    float4 v0 = *(const float4*)(W + i);
    float4 v1 = *(const float4*)(W + i + 4);
    __half2 h0 = __floats2half2_rn(v0.x, v0.y);
    __half2 h1 = __floats2half2_rn(v0.z, v0.w);
    __half2 h2 = __floats2half2_rn(v1.x, v1.y);
    __half2 h3 = __floats2half2_rn(v1.z, v1.w);
    uint4 o;
    o.x = *(uint32_t*)&h0; o.y = *(uint32_t*)&h1;
    o.z = *(uint32_t*)&h2; o.w = *(uint32_t*)&h3;
    *(uint4*)(dst + i) = o;
}

// X [b][ch][s] fp32 -> Xt [b][s][ch] half
__global__ void transpose_half_kernel(const float* __restrict__ X, __half* __restrict__ Xt) {
    __shared__ float tile[32][33];
    const int b  = blockIdx.z;
    const int k0 = blockIdx.y * 32;
    const int n0 = blockIdx.x * 32;
    const float* Xb  = X  + (size_t)b * CH * SSZ;
    __half*      Xtb = Xt + (size_t)b * SSZ * CH;
    const int tx = threadIdx.x & 31;
    const int ty = threadIdx.x >> 5;
#pragma unroll
    for (int i = 0; i < 4; i++)
        tile[ty + i * 8][tx] = Xb[(size_t)(k0 + ty + i * 8) * SSZ + n0 + tx];
    __syncthreads();
#pragma unroll
    for (int i = 0; i < 4; i++)
        Xtb[(size_t)(n0 + ty + i * 8) * CH + k0 + tx] =
            __float2half_rn(tile[tx][ty + i * 8]);
}

// ===========================================================================
// Persistent fp16 tensor-core GEMM (unchanged from R8)
// ===========================================================================
#define STAGE_B 32768
#define SMEM_G  (3 * STAGE_B)   // 98304

struct TileCtx {
    const __half* A;
    const __half* B;
    const float*  bias;
    float*  Yf;
    __half* Yh;
};

__global__ __launch_bounds__(128, 2) void gemm_persist(
    const __half* __restrict__ Wbase, const __half* __restrict__ Bbase,
    const float* __restrict__ b0, const float* __restrict__ b1,
    const float* __restrict__ b2,
    __half* __restrict__ H0, float* __restrict__ F1, __half* __restrict__ H1,
    float* __restrict__ F2, __half* __restrict__ H2,
    int mode, int ntiles)
{
    extern __shared__ char smem[];
    const uint32_t sb = smem_u32(smem);
    const int t    = threadIdx.x;
    const int lane = t & 31;
    const int wid  = t >> 5;
    const int wm   = wid >> 1;
    const int wn   = wid & 1;
    const int lr = t >> 3;
    const int lc = t & 7;

    auto decode = [&](int idx, TileCtx& c) {
        int x  = idx & 15;
        int n0 = x << 7;
        if (mode == 0) {
            int r = idx >> 4;
            int y = r % 96;
            int z = r / 96;
            int widx = y >> 5;
            int m0 = (y & 31) << 7;
            c.A = Wbase + (size_t)widx * WSZ + (size_t)m0 * CH;
            c.B = Bbase + (size_t)z * SSZ * CH + (size_t)n0 * CH;
            c.bias = ((widx == 0) ? b0 : (widx == 1) ? b1 : b2) + m0;
            size_t o = (size_t)z * CH * SSZ + (size_t)m0 * SSZ + n0;
            c.Yf = (widx == 0) ? (float*)0 : (((widx == 1) ? F1 : F2) + o);
            c.Yh = ((widx == 0) ? H0 : (widx == 1) ? H1 : H2) + o;
        } else {
            int y = (idx >> 4) & 31;
            int z = idx >> 9;
            int m0 = y << 7;
            c.A = Wbase + (size_t)m0 * CH;
            c.B = Bbase + (size_t)z * SSZ * CH + (size_t)n0 * CH;
            c.bias = b0 + m0;
            c.Yf = F1 + (size_t)z * CH * SSZ + (size_t)m0 * SSZ + n0;
            c.Yh = (__half*)0;
        }
    };

    TileCtx ictx;
    int itile  = blockIdx.x;
    int ichunk = 0;
    int istage = 0;
    bool ivalid = (itile < ntiles);
    if (ivalid) decode(itile, ictx);

    auto issue = [&]() {
        if (ivalid) {
            const int k0 = ichunk * 64;
            const uint32_t As = sb + istage * STAGE_B;
            const uint32_t Bs = As + 16384;
#pragma unroll
            for (int it = 0; it < 8; it++) {
                int m = it * 16 + lr;
                cp16(As + (uint32_t)(m * 128 + ((lc ^ (m & 7)) << 4)),
                     ictx.A + (size_t)m * CH + k0 + lc * 8);
            }
#pragma unroll
            for (int it = 0; it < 8; it++) {
                int n = it * 16 + lr;
                cp16(Bs + (uint32_t)(n * 128 + ((lc ^ (n & 7)) << 4)),
                     ictx.B + (size_t)n * CH + k0 + lc * 8);
            }
            istage = (istage == 2) ? 0 : istage + 1;
            if (++ichunk == 64) {
                ichunk = 0;
                itile += gridDim.x;
                ivalid = (itile < ntiles);
                if (ivalid) decode(itile, ictx);
            }
        }
        CP_COMMIT();
    };

    issue(); issue(); issue();
    int cstage = 0;

    for (int tt = blockIdx.x; tt < ntiles; tt += gridDim.x) {
        TileCtx cc;
        decode(tt, cc);

        float acc[4][8][4];
#pragma unroll
        for (int mt = 0; mt < 4; mt++)
#pragma unroll
            for (int nt = 0; nt < 8; nt++)
#pragma unroll
                for (int x = 0; x < 4; x++) acc[mt][nt][x] = 0.0f;

        for (int i = 0; i < 64; i++) {
            CP_WAIT(2);
            __syncthreads();
            const uint32_t As = sb + cstage * STAGE_B;
            const uint32_t Bs = As + 16384;
#pragma unroll
            for (int ks = 0; ks < 4; ks++) {
                uint32_t a[4][4], b[4][4];
#pragma unroll
                for (int mt = 0; mt < 4; mt++) {
                    int row = wm * 64 + mt * 16 + (lane & 15);
                    int ch  = ks * 2 + (lane >> 4);
                    ldsm_x4(a[mt][0], a[mt][1], a[mt][2], a[mt][3],
                            As + row * 128 + ((ch ^ (row & 7)) << 4));
                }
#pragma unroll
                for (int p = 0; p < 4; p++) {
                    int row = wn * 64 + p * 16 + ((lane >> 4) << 3) + (lane & 7);
                    int ch  = ks * 2 + ((lane >> 3) & 1);
                    ldsm_x4(b[p][0], b[p][1], b[p][2], b[p][3],
                            Bs + row * 128 + ((ch ^ (row & 7)) << 4));
                }
#pragma unroll
                for (int mt = 0; mt < 4; mt++)
#pragma unroll
                    for (int nt = 0; nt < 8; nt++)
                        mma_f16(acc[mt][nt], a[mt], &b[nt >> 1][(nt & 1) * 2]);
            }
            __syncthreads();
            cstage = (cstage == 2) ? 0 : cstage + 1;
            issue();
        }

        const int r  = lane >> 2;
        const int c4 = lane & 3;
#pragma unroll
        for (int mt = 0; mt < 4; mt++) {
            int rr = wm * 64 + mt * 16 + r;
            float bv0 = cc.bias[rr];
            float bv1 = cc.bias[rr + 8];
#pragma unroll
            for (int nt = 0; nt < 8; nt++) {
                int col = wn * 64 + nt * 8 + c4 * 2;
                float f00 = acc[mt][nt][0] + bv0, f01 = acc[mt][nt][1] + bv0;
                float f10 = acc[mt][nt][2] + bv1, f11 = acc[mt][nt][3] + bv1;
                if (cc.Yf) {
                    *(float2*)&cc.Yf[(size_t)rr * SSZ + col]       = make_float2(f00, f01);
                    *(float2*)&cc.Yf[(size_t)(rr + 8) * SSZ + col] = make_float2(f10, f11);
                }
                if (cc.Yh) {
                    __half2 h0 = __floats2half2_rn(f00, f01);
                    __half2 h1 = __floats2half2_rn(f10, f11);
                    *(__half2*)&cc.Yh[(size_t)rr * SSZ + col]       = h0;
                    *(__half2*)&cc.Yh[(size_t)(rr + 8) * SSZ + col] = h1;
                }
            }
        }
    }
}

// ===========================================================================
// Tensor-core attention v2: 2 CTAs per head (M-split), 256 threads, 2 CTA/SM.
// CTA handles 64 score rows (d-rows m0 = (cta&1)*64) x 128 cols.
// SMEM (112KB):
//   phase1 stages: 3 x 24KB (A=Q 64x128B @+0, B=K 128x128B @+8K) at [0,72K)
//   scores fp32 64x128: [0,32K)   (written after phase1 compute)
//   V bufs:  [32K,64K), [64K,96K)
//   P half 64 rows x 256B: [96K,112K)
//   OT stage 128x128B: [0,16K)    (after P built)
// ===========================================================================
#define ATT_STAGE 24576
#define ATT_OFF_V 32768
#define ATT_OFF_P 98304
#define ATT_SMEM  114688

__global__ __launch_bounds__(256, 2) void attn_tc2(
    const __half* __restrict__ Qh, const __half* __restrict__ Kh,
    const __half* __restrict__ Vh, __half* __restrict__ OT)
{
    extern __shared__ char smem[];
    const uint32_t sb = smem_u32(smem);
    float*  scores = (float*)smem;
    __half* Pp     = (__half*)(smem + ATT_OFF_P);
    const uint32_t Pb = sb + ATT_OFF_P;

    const int cta   = blockIdx.x;        // 0..255
    const int bh    = cta >> 1;
    const int m0    = (cta & 1) * 64;    // local d-row offset
    const int b_ = bh >> 5, h_ = bh & 31;
    const size_t hb = ((size_t)b_ * CH + (size_t)h_ * HD) * SSZ;
    const __half* q = Qh + hb + (size_t)m0 * SSZ;
    const __half* k = Kh + hb;
    const __half* v = Vh + hb;
    __half* oT = OT + (size_t)b_ * SSZ * CH + h_ * HD + m0;

    const int t    = threadIdx.x;
    const int lane = t & 31;
    const int wid  = t >> 5;     // 0..7
    const int wm   = wid >> 2;   // 0..1 (32 rows each)
    const int wn   = wid & 3;    // 0..3 (32 cols each)
    const int lr = t >> 3;       // 0..31
    const int lc = t & 7;

    float acc[2][4][4];
#pragma unroll
    for (int mt = 0; mt < 2; mt++)
#pragma unroll
        for (int nt = 0; nt < 4; nt++)
#pragma unroll
            for (int x = 0; x < 4; x++) acc[mt][nt][x] = 0.0f;

    // ---------------- Phase 1: scores[64x128] = Q[m0:m0+64] @ K^T ----------
    auto issue1 = [&](int chunk) {
        const int stage = chunk % 3;
        const int k0 = chunk * 64;
        const uint32_t As = sb + stage * ATT_STAGE;
        const uint32_t Bs = As + 8192;
#pragma unroll
        for (int it = 0; it < 2; it++) {
            int m = it * 32 + lr;
            cp16(As + (uint32_t)(m * 128 + ((lc ^ (m & 7)) << 4)),
                 q + (size_t)m * SSZ + k0 + lc * 8);
        }
#pragma unroll
        for (int it = 0; it < 4; it++) {
            int n = it * 32 + lr;
            cp16(Bs + (uint32_t)(n * 128 + ((lc ^ (n & 7)) << 4)),
                 k + (size_t)n * SSZ + k0 + lc * 8);
        }
        CP_COMMIT();
    };
    issue1(0); issue1(1); issue1(2);

    for (int i = 0; i < 32; i++) {
        CP_WAIT(2);
        __syncthreads();
        const uint32_t As = sb + (i % 3) * ATT_STAGE;
        const uint32_t Bs = As + 8192;
#pragma unroll
        for (int ks = 0; ks < 4; ks++) {
            uint32_t a[2][4], b[2][4];
#pragma unroll
            for (int mt = 0; mt < 2; mt++) {
                int row = wm * 32 + mt * 16 + (lane & 15);
                int ch  = ks * 2 + (lane >> 4);
                ldsm_x4(a[mt][0], a[mt][1], a[mt][2], a[mt][3],
                        As + row * 128 + ((ch ^ (row & 7)) << 4));
            }
#pragma unroll
            for (int p = 0; p < 2; p++) {
                int row = wn * 32 + p * 16 + ((lane >> 4) << 3) + (lane & 7);
                int ch  = ks * 2 + ((lane >> 3) & 1);
                ldsm_x4(b[p][0], b[p][1], b[p][2], b[p][3],
                        Bs + row * 128 + ((ch ^ (row & 7)) << 4));
            }
#pragma unroll
            for (int mt = 0; mt < 2; mt++)
#pragma unroll
                for (int nt = 0; nt < 4; nt++)
                    mma_f16(acc[mt][nt], a[mt], &b[nt >> 1][(nt & 1) * 2]);
        }
        __syncthreads();
        if (i + 3 < 32) issue1(i + 3);
        else CP_COMMIT();
    }
    CP_WAIT(0);
    __syncthreads();   // all reads done before scores overwrite stage area

    // scale + causal mask -> scores fp32 (local rows 0..63)
    {
        const float scale = rsqrtf((float)SSZ);
        const int r = lane >> 2;
        const int c = lane & 3;
#pragma unroll
        for (int mt = 0; mt < 2; mt++) {
            int row0 = wm * 32 + mt * 16 + r;
            int row1 = row0 + 8;
            int g0 = m0 + row0, g1 = m0 + row1;
#pragma unroll
            for (int nt = 0; nt < 4; nt++) {
                int col = wn * 32 + nt * 8 + c * 2;
                scores[row0 * 128 + col]     = (col     <= g0) ? acc[mt][nt][0] * scale : -1e30f;
                scores[row0 * 128 + col + 1] = (col + 1 <= g0) ? acc[mt][nt][1] * scale : -1e30f;
                scores[row1 * 128 + col]     = (col     <= g1) ? acc[mt][nt][2] * scale : -1e30f;
                scores[row1 * 128 + col + 1] = (col + 1 <= g1) ? acc[mt][nt][3] * scale : -1e30f;
            }
        }
    }
    __syncthreads();

    // kick off V chunk 0 (buffer does not overlap scores) — overlaps softmax
    auto issueV = [&](int nc) {
        const uint32_t Vb = sb + ATT_OFF_V + (nc & 1) * 32768;
        const int n0 = nc * 128;
#pragma unroll
        for (int i = 0; i < 8; i++) {
            int idx = i * 256 + t;
            int e = idx >> 4;
            int c = idx & 15;
            cp16(Vb + (uint32_t)(e * 256 + ((c ^ (e & 7)) << 4)),
                 v + (size_t)e * SSZ + n0 + c * 8);
        }
        CP_COMMIT();
    };
    issueV(0);

    // ---------------- Softmax: warp per 8 rows -> P half (swizzled) --------
#pragma unroll
    for (int rr = 0; rr < 8; rr++) {
        int row = wid * 8 + rr;
        float v0 = scores[row * 128 + lane];
        float v1 = scores[row * 128 + lane + 32];
        float v2 = scores[row * 128 + lane + 64];
        float v3 = scores[row * 128 + lane + 96];
        float mx = fmaxf(fmaxf(v0, v1), fmaxf(v2, v3));
#pragma unroll
        for (int o = 16; o > 0; o >>= 1)
            mx = fmaxf(mx, __shfl_xor_sync(0xFFFFFFFFu, mx, o));
        float e0 = __expf(v0 - mx), e1 = __expf(v1 - mx);
        float e2 = __expf(v2 - mx), e3 = __expf(v3 - mx);
        float sm = e0 + e1 + e2 + e3;
#pragma unroll
        for (int o = 16; o > 0; o >>= 1)
            sm += __shfl_xor_sync(0xFFFFFFFFu, sm, o);
        float inv = 1.0f / sm;
        float ev[4] = {e0, e1, e2, e3};
#pragma unroll
        for (int j = 0; j < 4; j++) {
            int col = lane + 32 * j;
            int hidx = row * 128 + ((((col >> 3) ^ (row & 7))) << 3) + (col & 7);
            Pp[hidx] = __float2half_rn(ev[j] * inv);
        }
    }

    __half* OTp = (__half*)smem;   // reuse scores region (16KB)

    // ---------------- Phase 2: attnT = (P[64x128] @ V)^T, 16 s-chunks -------
    for (int nc = 0; nc < 16; nc++) {
        if (nc + 1 < 16) { issueV(nc + 1); CP_WAIT(1); }
        else             { CP_WAIT(0); }
        __syncthreads();

        const uint32_t Vb = sb + ATT_OFF_V + (nc & 1) * 32768;
        float acc2[2][4][4];
#pragma unroll
        for (int mt = 0; mt < 2; mt++)
#pragma unroll
            for (int nt = 0; nt < 4; nt++)
#pragma unroll
                for (int x = 0; x < 4; x++) acc2[mt][nt][x] = 0.0f;

#pragma unroll
        for (int ks = 0; ks < 8; ks++) {
            uint32_t a[2][4], b[2][4];
#pragma unroll
            for (int mt = 0; mt < 2; mt++) {
                int row = wm * 32 + mt * 16 + (lane & 15);
                int ch  = ks * 2 + (lane >> 4);
                ldsm_x4(a[mt][0], a[mt][1], a[mt][2], a[mt][3],
                        Pb + row * 256 + ((ch ^ (row & 7)) << 4));
            }
#pragma unroll
            for (int p = 0; p < 2; p++) {
                int nb  = wn * 32 + p * 16;
                int grp = lane >> 3;
                int li  = lane & 7;
                int e   = ks * 16 + ((grp & 1) << 3) + li;
                int ncol = nb + ((grp >> 1) << 3);
                ldsm_x4_t(b[p][0], b[p][1], b[p][2], b[p][3],
                          Vb + e * 256 + (((ncol >> 3) ^ (e & 7)) << 4));
            }
#pragma unroll
            for (int mt = 0; mt < 2; mt++)
#pragma unroll
                for (int nt = 0; nt < 4; nt++)
                    mma_f16(acc2[mt][nt], a[mt], &b[nt >> 1][(nt & 1) * 2]);
        }

        // stage attnT tile [s(128)][d(64)] half, row = 128B
        {
            const int r = lane >> 2;
            const int c = lane & 3;
#pragma unroll
            for (int mt = 0; mt < 2; mt++) {
                int row0 = wm * 32 + mt * 16 + r;
#pragma unroll
                for (int nt = 0; nt < 4; nt++) {
                    int col = wn * 32 + nt * 8 + c * 2;
                    OTp[col * 64 + row0]           = __float2half_rn(acc2[mt][nt][0]);
                    OTp[(col + 1) * 64 + row0]     = __float2half_rn(acc2[mt][nt][1]);
                    OTp[col * 64 + row0 + 8]       = __float2half_rn(acc2[mt][nt][2]);
                    OTp[(col + 1) * 64 + row0 + 8] = __float2half_rn(acc2[mt][nt][3]);
                }
            }
        }
        __syncthreads();

        // coalesced global store: 128 s-rows x 128B (64B per thread)
        {
            int s  = t >> 1;
            int dp = (t & 1) * 32;   // halves
            const uint4* src = (const uint4*)(OTp + s * 64 + dp);
            uint4* dst = (uint4*)(oT + (size_t)(nc * 128 + s) * CH + dp);
#pragma unroll
            for (int u = 0; u < 4; u++) dst[u] = src[u];
        }
        __syncthreads();
    }
}

// ===========================================================================
// Launch
// ===========================================================================
extern "C" void kernel_launch(void* const* d_in, const int* in_sizes, int n_in,
                              void* d_out, int out_size)
{
    const float* hs = (const float*)d_in[0];
    const float* Wq = (const float*)d_in[1];
    const float* bq = (const float*)d_in[2];
    const float* Wk = (const float*)d_in[3];
    const float* bk = (const float*)d_in[4];
    const float* Wv = (const float*)d_in[5];
    const float* bv = (const float*)d_in[6];
    const float* Wo = (const float*)d_in[7];
    const float* bo = (const float*)d_in[8];

    float *kfb, *vfb;
    __half *qh, *kh, *vh, *atbufh, *xth, *wh;
    cudaGetSymbolAddress((void**)&qh,     g_qh);
    cudaGetSymbolAddress((void**)&kh,     g_kh);
    cudaGetSymbolAddress((void**)&vh,     g_vh);
    cudaGetSymbolAddress((void**)&atbufh, g_attnTh);
    cudaGetSymbolAddress((void**)&xth,    g_xth);
    cudaGetSymbolAddress((void**)&wh,     g_wh);
    cudaGetSymbolAddress((void**)&kfb,    g_kfb);
    cudaGetSymbolAddress((void**)&vfb,    g_vfb);

    float* out = (float*)d_out;
    float* kout;
    float* vout;
    if ((long long)out_size >= 3LL * BHS) {
        kout = out + (size_t)BHS;
        vout = out + 2 * (size_t)BHS;
    } else {
        kout = kfb;
        vout = vfb;
    }

    int sms = 148;
    cudaDeviceGetAttribute(&sms, cudaDevAttrMultiProcessorCount, 0);
    const int pgrid = 2 * sms;

    // ---- Prep ----
    round_half4_kernel<<<dim3(WSZ / (256 * 8), 4), 256>>>(Wq, Wk, Wv, Wo, wh);
    transpose_half_kernel<<<dim3(SSZ / 32, CH / 32, BB), 256>>>(hs, xth);

    // ---- Persistent Q/K/V projections (6144 tiles) ----
    cudaFuncSetAttribute(gemm_persist,
                         cudaFuncAttributeMaxDynamicSharedMemorySize, SMEM_G);
    gemm_persist<<<pgrid, 128, SMEM_G>>>(
        wh, xth, bq, bk, bv, qh, kout, kh, vout, vh, 0, 6144);

    // ---- Tensor-core attention (2 CTAs per head) ----
    cudaFuncSetAttribute(attn_tc2,
                         cudaFuncAttributeMaxDynamicSharedMemorySize, ATT_SMEM);
    attn_tc2<<<BB * NH * 2, 256, ATT_SMEM>>>(qh, kh, vh, atbufh);

    // ---- Persistent output projection (2048 tiles) ----
    gemm_persist<<<pgrid, 128, SMEM_G>>>(
        wh + 3 * (size_t)WSZ, atbufh, bo, (const float*)0, (const float*)0,
        (__half*)0, out, (__half*)0, (float*)0, (__half*)0, 1, 2048);
}

// round 10
// speedup vs baseline: 1.1807x; 1.0240x over previous
#include <cuda_runtime.h>
#include <cuda_fp16.h>
#include <math.h>
#include <stdint.h>

// Problem constants
#define BB 4
#define CH 4096     // HID
#define SSZ 2048    // S
#define NH 32       // heads
#define HD 128      // head dim

#define BHS 33554432   // BB*CH*SSZ elements
#define WSZ 16777216   // CH*CH elements

// Scratch (allocation-free rule: __device__ globals)
__device__ __half g_qh[BHS];      // Q half [b][ch][s]
__device__ __half g_kh[BHS];      // K half [b][ch][s]
__device__ __half g_vh[BHS];      // V half [b][ch][s]
__device__ __half g_attnTh[BHS];  // attention out, transposed half [b][s][ch]
__device__ __half g_xth[BHS];     // hidden transposed half [b][s][ch]
__device__ __half g_wh[4 * WSZ];  // half Wq,Wk,Wv,Wo (row-major, K-contig)
__device__ float  g_kfb[BHS];     // fallback K dest
__device__ float  g_vfb[BHS];     // fallback V dest

// ===========================================================================
// Helpers
// ===========================================================================
__device__ __forceinline__ uint32_t smem_u32(const void* p) {
    uint32_t a;
    asm("{ .reg .u64 t; cvta.to.shared.u64 t, %1; cvt.u32.u64 %0, t; }"
        : "=r"(a) : "l"(p));
    return a;
}

__device__ __forceinline__ void cp16(uint32_t dst, const void* src) {
    asm volatile("cp.async.cg.shared.global [%0], [%1], 16;"
                 :: "r"(dst), "l"(src) : "memory");
}
#define CP_COMMIT() asm volatile("cp.async.commit_group;" ::: "memory")
#define CP_WAIT(n)  asm volatile("cp.async.wait_group %0;" :: "n"(n) : "memory")

__device__ __forceinline__ void ldsm_x4(uint32_t& r0, uint32_t& r1,
                                        uint32_t& r2, uint32_t& r3, uint32_t addr) {
    asm volatile("ldmatrix.sync.aligned.m8n8.x4.shared.b16 {%0,%1,%2,%3}, [%4];"
                 : "=r"(r0), "=r"(r1), "=r"(r2), "=r"(r3) : "r"(addr));
}

__device__ __forceinline__ void ldsm_x4_t(uint32_t& r0, uint32_t& r1,
                                          uint32_t& r2, uint32_t& r3, uint32_t addr) {
    asm volatile("ldmatrix.sync.aligned.m8n8.x4.trans.shared.b16 {%0,%1,%2,%3}, [%4];"
                 : "=r"(r0), "=r"(r1), "=r"(r2), "=r"(r3) : "r"(addr));
}

// mma m16n8k16 f16 inputs, f32 accumulate
__device__ __forceinline__ void mma_f16(float* d, const uint32_t* a, const uint32_t* b) {
    asm volatile(
        "mma.sync.aligned.m16n8k16.row.col.f32.f16.f16.f32 "
        "{%0,%1,%2,%3}, {%4,%5,%6,%7}, {%8,%9}, {%0,%1,%2,%3};"
        : "+f"(d[0]), "+f"(d[1]), "+f"(d[2]), "+f"(d[3])
        : "r"(a[0]), "r"(a[1]), "r"(a[2]), "r"(a[3]), "r"(b[0]), "r"(b[1]));
}

// ===========================================================================
// Prep kernels
// ===========================================================================
__global__ void round_half4_kernel(
    const float* __restrict__ W0, const float* __restrict__ W1,
    const float* __restrict__ W2, const float* __restrict__ W3,
    __half* __restrict__ Wh)
{
    const float* W = (blockIdx.y == 0) ? W0 : (blockIdx.y == 1) ? W1
                   : (blockIdx.y == 2) ? W2 : W3;
    __half* dst = Wh + (size_t)blockIdx.y * WSZ;
    size_t i = ((size_t)blockIdx.x * 256 + threadIdx.x) * 8;
    float4 v0 = *(const float4*)(W + i);
    float4 v1 = *(const float4*)(W + i + 4);
    __half2 h0 = __floats2half2_rn(v0.x, v0.y);
    __half2 h1 = __floats2half2_rn(v0.z, v0.w);
    __half2 h2 = __floats2half2_rn(v1.x, v1.y);
    __half2 h3 = __floats2half2_rn(v1.z, v1.w);
    uint4 o;
    o.x = *(uint32_t*)&h0; o.y = *(uint32_t*)&h1;
    o.z = *(uint32_t*)&h2; o.w = *(uint32_t*)&h3;
    *(uint4*)(dst + i) = o;
}

// X [b][ch][s] fp32 -> Xt [b][s][ch] half
__global__ void transpose_half_kernel(const float* __restrict__ X, __half* __restrict__ Xt) {
    __shared__ float tile[32][33];
    const int b  = blockIdx.z;
    const int k0 = blockIdx.y * 32;
    const int n0 = blockIdx.x * 32;
    const float* Xb  = X  + (size_t)b * CH * SSZ;
    __half*      Xtb = Xt + (size_t)b * SSZ * CH;
    const int tx = threadIdx.x & 31;
    const int ty = threadIdx.x >> 5;
#pragma unroll
    for (int i = 0; i < 4; i++)
        tile[ty + i * 8][tx] = Xb[(size_t)(k0 + ty + i * 8) * SSZ + n0 + tx];
    __syncthreads();
#pragma unroll
    for (int i = 0; i < 4; i++)
        Xtb[(size_t)(n0 + ty + i * 8) * CH + k0 + tx] =
            __float2half_rn(tile[tx][ty + i * 8]);
}

// ===========================================================================
// Persistent fp16 tensor-core GEMM — single-barrier mainloop.
// Issue cursor runs 2 STAGES ahead (not 3): issue at iter i writes stage
// (i+2)%3, disjoint from the stage being read (i%3) and the next (i+1)%3,
// so the post-compute __syncthreads is unnecessary; warp skew is bounded
// by the single top-of-iteration barrier.
// ===========================================================================
#define STAGE_B 32768
#define SMEM_G  (3 * STAGE_B)   // 98304

struct TileCtx {
    const __half* A;
    const __half* B;
    const float*  bias;
    float*  Yf;
    __half* Yh;
};

__global__ __launch_bounds__(128, 2) void gemm_persist(
    const __half* __restrict__ Wbase, const __half* __restrict__ Bbase,
    const float* __restrict__ b0, const float* __restrict__ b1,
    const float* __restrict__ b2,
    __half* __restrict__ H0, float* __restrict__ F1, __half* __restrict__ H1,
    float* __restrict__ F2, __half* __restrict__ H2,
    int mode, int ntiles)
{
    extern __shared__ char smem[];
    const uint32_t sb = smem_u32(smem);
    const int t    = threadIdx.x;
    const int lane = t & 31;
    const int wid  = t >> 5;
    const int wm   = wid >> 1;
    const int wn   = wid & 1;
    const int lr = t >> 3;
    const int lc = t & 7;

    auto decode = [&](int idx, TileCtx& c) {
        int x  = idx & 15;
        int n0 = x << 7;
        if (mode == 0) {
            int r = idx >> 4;
            int y = r % 96;
            int z = r / 96;
            int widx = y >> 5;
            int m0 = (y & 31) << 7;
            c.A = Wbase + (size_t)widx * WSZ + (size_t)m0 * CH;
            c.B = Bbase + (size_t)z * SSZ * CH + (size_t)n0 * CH;
            c.bias = ((widx == 0) ? b0 : (widx == 1) ? b1 : b2) + m0;
            size_t o = (size_t)z * CH * SSZ + (size_t)m0 * SSZ + n0;
            c.Yf = (widx == 0) ? (float*)0 : (((widx == 1) ? F1 : F2) + o);
            c.Yh = ((widx == 0) ? H0 : (widx == 1) ? H1 : H2) + o;
        } else {
            int y = (idx >> 4) & 31;
            int z = idx >> 9;
            int m0 = y << 7;
            c.A = Wbase + (size_t)m0 * CH;
            c.B = Bbase + (size_t)z * SSZ * CH + (size_t)n0 * CH;
            c.bias = b0 + m0;
            c.Yf = F1 + (size_t)z * CH * SSZ + (size_t)m0 * SSZ + n0;
            c.Yh = (__half*)0;
        }
    };

    // ---- issue cursor (2 chunks ahead of compute, crosses tile boundaries)
    TileCtx ictx;
    int itile  = blockIdx.x;
    int ichunk = 0;
    int istage = 0;
    bool ivalid = (itile < ntiles);
    if (ivalid) decode(itile, ictx);

    auto issue = [&]() {
        if (ivalid) {
            const int k0 = ichunk * 64;
            const uint32_t As = sb + istage * STAGE_B;
            const uint32_t Bs = As + 16384;
#pragma unroll
            for (int it = 0; it < 8; it++) {
                int m = it * 16 + lr;
                cp16(As + (uint32_t)(m * 128 + ((lc ^ (m & 7)) << 4)),
                     ictx.A + (size_t)m * CH + k0 + lc * 8);
            }
#pragma unroll
            for (int it = 0; it < 8; it++) {
                int n = it * 16 + lr;
                cp16(Bs + (uint32_t)(n * 128 + ((lc ^ (n & 7)) << 4)),
                     ictx.B + (size_t)n * CH + k0 + lc * 8);
            }
            istage = (istage == 2) ? 0 : istage + 1;
            if (++ichunk == 64) {
                ichunk = 0;
                itile += gridDim.x;
                ivalid = (itile < ntiles);
                if (ivalid) decode(itile, ictx);
            }
        }
        CP_COMMIT();
    };

    issue(); issue();    // depth-2 prefetch
    int cstage = 0;

    for (int tt = blockIdx.x; tt < ntiles; tt += gridDim.x) {
        TileCtx cc;
        decode(tt, cc);

        float acc[4][8][4];
#pragma unroll
        for (int mt = 0; mt < 4; mt++)
#pragma unroll
            for (int nt = 0; nt < 8; nt++)
#pragma unroll
                for (int x = 0; x < 4; x++) acc[mt][nt][x] = 0.0f;

        for (int i = 0; i < 64; i++) {
            CP_WAIT(1);
            __syncthreads();        // single barrier per iteration
            const uint32_t As = sb + cstage * STAGE_B;
            const uint32_t Bs = As + 16384;
#pragma unroll
            for (int ks = 0; ks < 4; ks++) {
                uint32_t a[4][4], b[4][4];
#pragma unroll
                for (int mt = 0; mt < 4; mt++) {
                    int row = wm * 64 + mt * 16 + (lane & 15);
                    int ch  = ks * 2 + (lane >> 4);
                    ldsm_x4(a[mt][0], a[mt][1], a[mt][2], a[mt][3],
                            As + row * 128 + ((ch ^ (row & 7)) << 4));
                }
#pragma unroll
                for (int p = 0; p < 4; p++) {
                    int row = wn * 64 + p * 16 + ((lane >> 4) << 3) + (lane & 7);
                    int ch  = ks * 2 + ((lane >> 3) & 1);
                    ldsm_x4(b[p][0], b[p][1], b[p][2], b[p][3],
                            Bs + row * 128 + ((ch ^ (row & 7)) << 4));
                }
#pragma unroll
                for (int mt = 0; mt < 4; mt++)
#pragma unroll
                    for (int nt = 0; nt < 8; nt++)
                        mma_f16(acc[mt][nt], a[mt], &b[nt >> 1][(nt & 1) * 2]);
            }
            cstage = (cstage == 2) ? 0 : cstage + 1;
            issue();                // writes stage (i+2)%3: disjoint, no bar needed
        }

        // Epilogue: direct reg->global; overlaps next tile's in-flight cp.async
        const int r  = lane >> 2;
        const int c4 = lane & 3;
#pragma unroll
        for (int mt = 0; mt < 4; mt++) {
            int rr = wm * 64 + mt * 16 + r;
            float bv0 = cc.bias[rr];
            float bv1 = cc.bias[rr + 8];
#pragma unroll
            for (int nt = 0; nt < 8; nt++) {
                int col = wn * 64 + nt * 8 + c4 * 2;
                float f00 = acc[mt][nt][0] + bv0, f01 = acc[mt][nt][1] + bv0;
                float f10 = acc[mt][nt][2] + bv1, f11 = acc[mt][nt][3] + bv1;
                if (cc.Yf) {
                    *(float2*)&cc.Yf[(size_t)rr * SSZ + col]       = make_float2(f00, f01);
                    *(float2*)&cc.Yf[(size_t)(rr + 8) * SSZ + col] = make_float2(f10, f11);
                }
                if (cc.Yh) {
                    __half2 h0 = __floats2half2_rn(f00, f01);
                    __half2 h1 = __floats2half2_rn(f10, f11);
                    *(__half2*)&cc.Yh[(size_t)rr * SSZ + col]       = h0;
                    *(__half2*)&cc.Yh[(size_t)(rr + 8) * SSZ + col] = h1;
                }
            }
        }
    }
}

// ===========================================================================
// Tensor-core attention v2 (unchanged from R9): 2 CTAs per head, 256 thr.
// ===========================================================================
#define ATT_STAGE 24576
#define ATT_OFF_V 32768
#define ATT_OFF_P 98304
#define ATT_SMEM  114688

__global__ __launch_bounds__(256, 2) void attn_tc2(
    const __half* __restrict__ Qh, const __half* __restrict__ Kh,
    const __half* __restrict__ Vh, __half* __restrict__ OT)
{
    extern __shared__ char smem[];
    const uint32_t sb = smem_u32(smem);
    float*  scores = (float*)smem;
    __half* Pp     = (__half*)(smem + ATT_OFF_P);
    const uint32_t Pb = sb + ATT_OFF_P;

    const int cta   = blockIdx.x;
    const int bh    = cta >> 1;
    const int m0    = (cta & 1) * 64;
    const int b_ = bh >> 5, h_ = bh & 31;
    const size_t hb = ((size_t)b_ * CH + (size_t)h_ * HD) * SSZ;
    const __half* q = Qh + hb + (size_t)m0 * SSZ;
    const __half* k = Kh + hb;
    const __half* v = Vh + hb;
    __half* oT = OT + (size_t)b_ * SSZ * CH + h_ * HD + m0;

    const int t    = threadIdx.x;
    const int lane = t & 31;
    const int wid  = t >> 5;
    const int wm   = wid >> 2;
    const int wn   = wid & 3;
    const int lr = t >> 3;
    const int lc = t & 7;

    float acc[2][4][4];
#pragma unroll
    for (int mt = 0; mt < 2; mt++)
#pragma unroll
        for (int nt = 0; nt < 4; nt++)
#pragma unroll
            for (int x = 0; x < 4; x++) acc[mt][nt][x] = 0.0f;

    auto issue1 = [&](int chunk) {
        const int stage = chunk % 3;
        const int k0 = chunk * 64;
        const uint32_t As = sb + stage * ATT_STAGE;
        const uint32_t Bs = As + 8192;
#pragma unroll
        for (int it = 0; it < 2; it++) {
            int m = it * 32 + lr;
            cp16(As + (uint32_t)(m * 128 + ((lc ^ (m & 7)) << 4)),
                 q + (size_t)m * SSZ + k0 + lc * 8);
        }
#pragma unroll
        for (int it = 0; it < 4; it++) {
            int n = it * 32 + lr;
            cp16(Bs + (uint32_t)(n * 128 + ((lc ^ (n & 7)) << 4)),
                 k + (size_t)n * SSZ + k0 + lc * 8);
        }
        CP_COMMIT();
    };
    issue1(0); issue1(1); issue1(2);

    for (int i = 0; i < 32; i++) {
        CP_WAIT(2);
        __syncthreads();
        const uint32_t As = sb + (i % 3) * ATT_STAGE;
        const uint32_t Bs = As + 8192;
#pragma unroll
        for (int ks = 0; ks < 4; ks++) {
            uint32_t a[2][4], b[2][4];
#pragma unroll
            for (int mt = 0; mt < 2; mt++) {
                int row = wm * 32 + mt * 16 + (lane & 15);
                int ch  = ks * 2 + (lane >> 4);
                ldsm_x4(a[mt][0], a[mt][1], a[mt][2], a[mt][3],
                        As + row * 128 + ((ch ^ (row & 7)) << 4));
            }
#pragma unroll
            for (int p = 0; p < 2; p++) {
                int row = wn * 32 + p * 16 + ((lane >> 4) << 3) + (lane & 7);
                int ch  = ks * 2 + ((lane >> 3) & 1);
                ldsm_x4(b[p][0], b[p][1], b[p][2], b[p][3],
                        Bs + row * 128 + ((ch ^ (row & 7)) << 4));
            }
#pragma unroll
            for (int mt = 0; mt < 2; mt++)
#pragma unroll
                for (int nt = 0; nt < 4; nt++)
                    mma_f16(acc[mt][nt], a[mt], &b[nt >> 1][(nt & 1) * 2]);
        }
        __syncthreads();
        if (i + 3 < 32) issue1(i + 3);
        else CP_COMMIT();
    }
    CP_WAIT(0);
    __syncthreads();

    {
        const float scale = rsqrtf((float)SSZ);
        const int r = lane >> 2;
        const int c = lane & 3;
#pragma unroll
        for (int mt = 0; mt < 2; mt++) {
            int row0 = wm * 32 + mt * 16 + r;
            int row1 = row0 + 8;
            int g0 = m0 + row0, g1 = m0 + row1;
#pragma unroll
            for (int nt = 0; nt < 4; nt++) {
                int col = wn * 32 + nt * 8 + c * 2;
                scores[row0 * 128 + col]     = (col     <= g0) ? acc[mt][nt][0] * scale : -1e30f;
                scores[row0 * 128 + col + 1] = (col + 1 <= g0) ? acc[mt][nt][1] * scale : -1e30f;
                scores[row1 * 128 + col]     = (col     <= g1) ? acc[mt][nt][2] * scale : -1e30f;
                scores[row1 * 128 + col + 1] = (col + 1 <= g1) ? acc[mt][nt][3] * scale : -1e30f;
            }
        }
    }
    __syncthreads();

    auto issueV = [&](int nc) {
        const uint32_t Vb = sb + ATT_OFF_V + (nc & 1) * 32768;
        const int n0 = nc * 128;
#pragma unroll
        for (int i = 0; i < 8; i++) {
            int idx = i * 256 + t;
            int e = idx >> 4;
            int c = idx & 15;
            cp16(Vb + (uint32_t)(e * 256 + ((c ^ (e & 7)) << 4)),
                 v + (size_t)e * SSZ + n0 + c * 8);
        }
        CP_COMMIT();
    };
    issueV(0);

#pragma unroll
    for (int rr = 0; rr < 8; rr++) {
        int row = wid * 8 + rr;
        float v0 = scores[row * 128 + lane];
        float v1 = scores[row * 128 + lane + 32];
        float v2 = scores[row * 128 + lane + 64];
        float v3 = scores[row * 128 + lane + 96];
        float mx = fmaxf(fmaxf(v0, v1), fmaxf(v2, v3));
#pragma unroll
        for (int o = 16; o > 0; o >>= 1)
            mx = fmaxf(mx, __shfl_xor_sync(0xFFFFFFFFu, mx, o));
        float e0 = __expf(v0 - mx), e1 = __expf(v1 - mx);
        float e2 = __expf(v2 - mx), e3 = __expf(v3 - mx);
        float sm = e0 + e1 + e2 + e3;
#pragma unroll
        for (int o = 16; o > 0; o >>= 1)
            sm += __shfl_xor_sync(0xFFFFFFFFu, sm, o);
        float inv = 1.0f / sm;
        float ev[4] = {e0, e1, e2, e3};
#pragma unroll
        for (int j = 0; j < 4; j++) {
            int col = lane + 32 * j;
            int hidx = row * 128 + ((((col >> 3) ^ (row & 7))) << 3) + (col & 7);
            Pp[hidx] = __float2half_rn(ev[j] * inv);
        }
    }

    __half* OTp = (__half*)smem;

    for (int nc = 0; nc < 16; nc++) {
        if (nc + 1 < 16) { issueV(nc + 1); CP_WAIT(1); }
        else             { CP_WAIT(0); }
        __syncthreads();

        const uint32_t Vb = sb + ATT_OFF_V + (nc & 1) * 32768;
        float acc2[2][4][4];
#pragma unroll
        for (int mt = 0; mt < 2; mt++)
#pragma unroll
            for (int nt = 0; nt < 4; nt++)
#pragma unroll
                for (int x = 0; x < 4; x++) acc2[mt][nt][x] = 0.0f;

#pragma unroll
        for (int ks = 0; ks < 8; ks++) {
            uint32_t a[2][4], b[2][4];
#pragma unroll
            for (int mt = 0; mt < 2; mt++) {
                int row = wm * 32 + mt * 16 + (lane & 15);
                int ch  = ks * 2 + (lane >> 4);
                ldsm_x4(a[mt][0], a[mt][1], a[mt][2], a[mt][3],
                        Pb + row * 256 + ((ch ^ (row & 7)) << 4));
            }
#pragma unroll
            for (int p = 0; p < 2; p++) {
                int nb  = wn * 32 + p * 16;
                int grp = lane >> 3;
                int li  = lane & 7;
                int e   = ks * 16 + ((grp & 1) << 3) + li;
                int ncol = nb + ((grp >> 1) << 3);
                ldsm_x4_t(b[p][0], b[p][1], b[p][2], b[p][3],
                          Vb + e * 256 + (((ncol >> 3) ^ (e & 7)) << 4));
            }
#pragma unroll
            for (int mt = 0; mt < 2; mt++)
#pragma unroll
                for (int nt = 0; nt < 4; nt++)
                    mma_f16(acc2[mt][nt], a[mt], &b[nt >> 1][(nt & 1) * 2]);
        }

        {
            const int r = lane >> 2;
            const int c = lane & 3;
#pragma unroll
            for (int mt = 0; mt < 2; mt++) {
                int row0 = wm * 32 + mt * 16 + r;
#pragma unroll
                for (int nt = 0; nt < 4; nt++) {
                    int col = wn * 32 + nt * 8 + c * 2;
                    OTp[col * 64 + row0]           = __float2half_rn(acc2[mt][nt][0]);
                    OTp[(col + 1) * 64 + row0]     = __float2half_rn(acc2[mt][nt][1]);
                    OTp[col * 64 + row0 + 8]       = __float2half_rn(acc2[mt][nt][2]);
                    OTp[(col + 1) * 64 + row0 + 8] = __float2half_rn(acc2[mt][nt][3]);
                }
            }
        }
        __syncthreads();

        {
            int s  = t >> 1;
            int dp = (t & 1) * 32;
            const uint4* src = (const uint4*)(OTp + s * 64 + dp);
            uint4* dst = (uint4*)(oT + (size_t)(nc * 128 + s) * CH + dp);
#pragma unroll
            for (int u = 0; u < 4; u++) dst[u] = src[u];
        }
        __syncthreads();
    }
}

// ===========================================================================
// Launch
// ===========================================================================
extern "C" void kernel_launch(void* const* d_in, const int* in_sizes, int n_in,
                              void* d_out, int out_size)
{
    const float* hs = (const float*)d_in[0];
    const float* Wq = (const float*)d_in[1];
    const float* bq = (const float*)d_in[2];
    const float* Wk = (const float*)d_in[3];
    const float* bk = (const float*)d_in[4];
    const float* Wv = (const float*)d_in[5];
    const float* bv = (const float*)d_in[6];
    const float* Wo = (const float*)d_in[7];
    const float* bo = (const float*)d_in[8];

    float *kfb, *vfb;
    __half *qh, *kh, *vh, *atbufh, *xth, *wh;
    cudaGetSymbolAddress((void**)&qh,     g_qh);
    cudaGetSymbolAddress((void**)&kh,     g_kh);
    cudaGetSymbolAddress((void**)&vh,     g_vh);
    cudaGetSymbolAddress((void**)&atbufh, g_attnTh);
    cudaGetSymbolAddress((void**)&xth,    g_xth);
    cudaGetSymbolAddress((void**)&wh,     g_wh);
    cudaGetSymbolAddress((void**)&kfb,    g_kfb);
    cudaGetSymbolAddress((void**)&vfb,    g_vfb);

    float* out = (float*)d_out;
    float* kout;
    float* vout;
    if ((long long)out_size >= 3LL * BHS) {
        kout = out + (size_t)BHS;
        vout = out + 2 * (size_t)BHS;
    } else {
        kout = kfb;
        vout = vfb;
    }

    int sms = 148;
    cudaDeviceGetAttribute(&sms, cudaDevAttrMultiProcessorCount, 0);
    const int pgrid = 2 * sms;

    // ---- Prep ----
    round_half4_kernel<<<dim3(WSZ / (256 * 8), 4), 256>>>(Wq, Wk, Wv, Wo, wh);
    transpose_half_kernel<<<dim3(SSZ / 32, CH / 32, BB), 256>>>(hs, xth);

    // ---- Persistent Q/K/V projections (6144 tiles) ----
    cudaFuncSetAttribute(gemm_persist,
                         cudaFuncAttributeMaxDynamicSharedMemorySize, SMEM_G);
    gemm_persist<<<pgrid, 128, SMEM_G>>>(
        wh, xth, bq, bk, bv, qh, kout, kh, vout, vh, 0, 6144);

    // ---- Tensor-core attention (2 CTAs per head) ----
    cudaFuncSetAttribute(attn_tc2,
                         cudaFuncAttributeMaxDynamicSharedMemorySize, ATT_SMEM);
    attn_tc2<<<BB * NH * 2, 256, ATT_SMEM>>>(qh, kh, vh, atbufh);

    // ---- Persistent output projection (2048 tiles) ----
    gemm_persist<<<pgrid, 128, SMEM_G>>>(
        wh + 3 * (size_t)WSZ, atbufh, bo, (const float*)0, (const float*)0,
        (__half*)0, out, (__half*)0, (float*)0, (__half*)0, 1, 2048);
}

// round 11
// speedup vs baseline: 1.1826x; 1.0016x over previous
#include <cuda_runtime.h>
#include <cuda_fp16.h>
#include <math.h>
#include <stdint.h>

// Problem constants
#define BB 4
#define CH 4096     // HID
#define SSZ 2048    // S
#define NH 32       // heads
#define HD 128      // head dim

#define BHS 33554432   // BB*CH*SSZ elements
#define WSZ 16777216   // CH*CH elements

// Scratch (allocation-free rule: __device__ globals)
__device__ __half g_qh[BHS];      // Q half [b][ch][s]
__device__ __half g_kh[BHS];      // K half [b][ch][s]
__device__ __half g_vh[BHS];      // V half [b][ch][s]
__device__ __half g_attnTh[BHS];  // attention out, transposed half [b][s][ch]
__device__ __half g_xth[BHS];     // hidden transposed half [b][s][ch]
__device__ __half g_wh[4 * WSZ];  // half Wq,Wk,Wv,Wo (row-major, K-contig)
__device__ float  g_kfb[BHS];     // fallback K dest
__device__ float  g_vfb[BHS];     // fallback V dest

// ===========================================================================
// Helpers
// ===========================================================================
__device__ __forceinline__ uint32_t smem_u32(const void* p) {
    uint32_t a;
    asm("{ .reg .u64 t; cvta.to.shared.u64 t, %1; cvt.u32.u64 %0, t; }"
        : "=r"(a) : "l"(p));
    return a;
}

__device__ __forceinline__ void cp16(uint32_t dst, const void* src) {
    asm volatile("cp.async.cg.shared.global [%0], [%1], 16;"
                 :: "r"(dst), "l"(src) : "memory");
}
#define CP_COMMIT() asm volatile("cp.async.commit_group;" ::: "memory")
#define CP_WAIT(n)  asm volatile("cp.async.wait_group %0;" :: "n"(n) : "memory")

__device__ __forceinline__ void ldsm_x4(uint32_t& r0, uint32_t& r1,
                                        uint32_t& r2, uint32_t& r3, uint32_t addr) {
    asm volatile("ldmatrix.sync.aligned.m8n8.x4.shared.b16 {%0,%1,%2,%3}, [%4];"
                 : "=r"(r0), "=r"(r1), "=r"(r2), "=r"(r3) : "r"(addr));
}

__device__ __forceinline__ void ldsm_x4_t(uint32_t& r0, uint32_t& r1,
                                          uint32_t& r2, uint32_t& r3, uint32_t addr) {
    asm volatile("ldmatrix.sync.aligned.m8n8.x4.trans.shared.b16 {%0,%1,%2,%3}, [%4];"
                 : "=r"(r0), "=r"(r1), "=r"(r2), "=r"(r3) : "r"(addr));
}

// mma m16n8k16 f16 inputs, f32 accumulate
__device__ __forceinline__ void mma_f16(float* d, const uint32_t* a, const uint32_t* b) {
    asm volatile(
        "mma.sync.aligned.m16n8k16.row.col.f32.f16.f16.f32 "
        "{%0,%1,%2,%3}, {%4,%5,%6,%7}, {%8,%9}, {%0,%1,%2,%3};"
        : "+f"(d[0]), "+f"(d[1]), "+f"(d[2]), "+f"(d[3])
        : "r"(a[0]), "r"(a[1]), "r"(a[2]), "r"(a[3]), "r"(b[0]), "r"(b[1]));
}

// ===========================================================================
// Prep kernels
// ===========================================================================
__global__ void round_half4_kernel(
    const float* __restrict__ W0, const float* __restrict__ W1,
    const float* __restrict__ W2, const float* __restrict__ W3,
    __half* __restrict__ Wh)
{
    const float* W = (blockIdx.y == 0) ? W0 : (blockIdx.y == 1) ? W1
                   : (blockIdx.y == 2) ? W2 : W3;
    __half* dst = Wh + (size_t)blockIdx.y * WSZ;
    size_t i = ((size_t)blockIdx.x * 256 + threadIdx.x) * 8;
    float4 v0 = *(const float4*)(W + i);
    float4 v1 = *(const float4*)(W + i + 4);
    __half2 h0 = __floats2half2_rn(v0.x, v0.y);
    __half2 h1 = __floats2half2_rn(v0.z, v0.w);
    __half2 h2 = __floats2half2_rn(v1.x, v1.y);
    __half2 h3 = __floats2half2_rn(v1.z, v1.w);
    uint4 o;
    o.x = *(uint32_t*)&h0; o.y = *(uint32_t*)&h1;
    o.z = *(uint32_t*)&h2; o.w = *(uint32_t*)&h3;
    *(uint4*)(dst + i) = o;
}

// X [b][ch][s] fp32 -> Xt [b][s][ch] half.
// 64ch x 32s tile per CTA: fp32 loads 128B-coalesced over s; half2 stores
// 128B-coalesced over ch (full-line writes, vs 64B/warp before).
__global__ void transpose_half_kernel(const float* __restrict__ X, __half* __restrict__ Xt) {
    __shared__ float tile[32][66];   // [s][ch], pad 66 keeps float2 reads 8B-aligned
    const int b  = blockIdx.z;
    const int k0 = blockIdx.y * 64;  // ch
    const int n0 = blockIdx.x * 32;  // s
    const float* Xb  = X  + (size_t)b * CH * SSZ;
    __half*      Xtb = Xt + (size_t)b * SSZ * CH;
    const int lane = threadIdx.x & 31;
    const int w    = threadIdx.x >> 5;   // 0..7
#pragma unroll
    for (int i = 0; i < 8; i++) {
        int ch = w * 8 + i;              // 0..63
        tile[lane][ch] = Xb[(size_t)(k0 + ch) * SSZ + n0 + lane];
    }
    __syncthreads();
#pragma unroll
    for (int j = 0; j < 4; j++) {
        int s = w * 4 + j;               // 0..31
        float2 v = *(const float2*)&tile[s][lane * 2];
        __half2 h = __floats2half2_rn(v.x, v.y);
        *(__half2*)&Xtb[(size_t)(n0 + s) * CH + k0 + lane * 2] = h;
    }
}

// ===========================================================================
// Persistent fp16 tensor-core GEMM — single-barrier mainloop (R10, unchanged)
// ===========================================================================
#define STAGE_B 32768
#define SMEM_G  (3 * STAGE_B)   // 98304

struct TileCtx {
    const __half* A;
    const __half* B;
    const float*  bias;
    float*  Yf;
    __half* Yh;
};

__global__ __launch_bounds__(128, 2) void gemm_persist(
    const __half* __restrict__ Wbase, const __half* __restrict__ Bbase,
    const float* __restrict__ b0, const float* __restrict__ b1,
    const float* __restrict__ b2,
    __half* __restrict__ H0, float* __restrict__ F1, __half* __restrict__ H1,
    float* __restrict__ F2, __half* __restrict__ H2,
    int mode, int ntiles)
{
    extern __shared__ char smem[];
    const uint32_t sb = smem_u32(smem);
    const int t    = threadIdx.x;
    const int lane = t & 31;
    const int wid  = t >> 5;
    const int wm   = wid >> 1;
    const int wn   = wid & 1;
    const int lr = t >> 3;
    const int lc = t & 7;

    auto decode = [&](int idx, TileCtx& c) {
        int x  = idx & 15;
        int n0 = x << 7;
        if (mode == 0) {
            int r = idx >> 4;
            int y = r % 96;
            int z = r / 96;
            int widx = y >> 5;
            int m0 = (y & 31) << 7;
            c.A = Wbase + (size_t)widx * WSZ + (size_t)m0 * CH;
            c.B = Bbase + (size_t)z * SSZ * CH + (size_t)n0 * CH;
            c.bias = ((widx == 0) ? b0 : (widx == 1) ? b1 : b2) + m0;
            size_t o = (size_t)z * CH * SSZ + (size_t)m0 * SSZ + n0;
            c.Yf = (widx == 0) ? (float*)0 : (((widx == 1) ? F1 : F2) + o);
            c.Yh = ((widx == 0) ? H0 : (widx == 1) ? H1 : H2) + o;
        } else {
            int y = (idx >> 4) & 31;
            int z = idx >> 9;
            int m0 = y << 7;
            c.A = Wbase + (size_t)m0 * CH;
            c.B = Bbase + (size_t)z * SSZ * CH + (size_t)n0 * CH;
            c.bias = b0 + m0;
            c.Yf = F1 + (size_t)z * CH * SSZ + (size_t)m0 * SSZ + n0;
            c.Yh = (__half*)0;
        }
    };

    TileCtx ictx;
    int itile  = blockIdx.x;
    int ichunk = 0;
    int istage = 0;
    bool ivalid = (itile < ntiles);
    if (ivalid) decode(itile, ictx);

    auto issue = [&]() {
        if (ivalid) {
            const int k0 = ichunk * 64;
            const uint32_t As = sb + istage * STAGE_B;
            const uint32_t Bs = As + 16384;
#pragma unroll
            for (int it = 0; it < 8; it++) {
                int m = it * 16 + lr;
                cp16(As + (uint32_t)(m * 128 + ((lc ^ (m & 7)) << 4)),
                     ictx.A + (size_t)m * CH + k0 + lc * 8);
            }
#pragma unroll
            for (int it = 0; it < 8; it++) {
                int n = it * 16 + lr;
                cp16(Bs + (uint32_t)(n * 128 + ((lc ^ (n & 7)) << 4)),
                     ictx.B + (size_t)n * CH + k0 + lc * 8);
            }
            istage = (istage == 2) ? 0 : istage + 1;
            if (++ichunk == 64) {
                ichunk = 0;
                itile += gridDim.x;
                ivalid = (itile < ntiles);
                if (ivalid) decode(itile, ictx);
            }
        }
        CP_COMMIT();
    };

    issue(); issue();    // depth-2 prefetch
    int cstage = 0;

    for (int tt = blockIdx.x; tt < ntiles; tt += gridDim.x) {
        TileCtx cc;
        decode(tt, cc);

        float acc[4][8][4];
#pragma unroll
        for (int mt = 0; mt < 4; mt++)
#pragma unroll
            for (int nt = 0; nt < 8; nt++)
#pragma unroll
                for (int x = 0; x < 4; x++) acc[mt][nt][x] = 0.0f;

        for (int i = 0; i < 64; i++) {
            CP_WAIT(1);
            __syncthreads();        // single barrier per iteration
            const uint32_t As = sb + cstage * STAGE_B;
            const uint32_t Bs = As + 16384;
#pragma unroll
            for (int ks = 0; ks < 4; ks++) {
                uint32_t a[4][4], b[4][4];
#pragma unroll
                for (int mt = 0; mt < 4; mt++) {
                    int row = wm * 64 + mt * 16 + (lane & 15);
                    int ch  = ks * 2 + (lane >> 4);
                    ldsm_x4(a[mt][0], a[mt][1], a[mt][2], a[mt][3],
                            As + row * 128 + ((ch ^ (row & 7)) << 4));
                }
#pragma unroll
                for (int p = 0; p < 4; p++) {
                    int row = wn * 64 + p * 16 + ((lane >> 4) << 3) + (lane & 7);
                    int ch  = ks * 2 + ((lane >> 3) & 1);
                    ldsm_x4(b[p][0], b[p][1], b[p][2], b[p][3],
                            Bs + row * 128 + ((ch ^ (row & 7)) << 4));
                }
#pragma unroll
                for (int mt = 0; mt < 4; mt++)
#pragma unroll
                    for (int nt = 0; nt < 8; nt++)
                        mma_f16(acc[mt][nt], a[mt], &b[nt >> 1][(nt & 1) * 2]);
            }
            cstage = (cstage == 2) ? 0 : cstage + 1;
            issue();                // writes stage (i+2)%3: disjoint, no bar needed
        }

        const int r  = lane >> 2;
        const int c4 = lane & 3;
#pragma unroll
        for (int mt = 0; mt < 4; mt++) {
            int rr = wm * 64 + mt * 16 + r;
            float bv0 = cc.bias[rr];
            float bv1 = cc.bias[rr + 8];
#pragma unroll
            for (int nt = 0; nt < 8; nt++) {
                int col = wn * 64 + nt * 8 + c4 * 2;
                float f00 = acc[mt][nt][0] + bv0, f01 = acc[mt][nt][1] + bv0;
                float f10 = acc[mt][nt][2] + bv1, f11 = acc[mt][nt][3] + bv1;
                if (cc.Yf) {
                    *(float2*)&cc.Yf[(size_t)rr * SSZ + col]       = make_float2(f00, f01);
                    *(float2*)&cc.Yf[(size_t)(rr + 8) * SSZ + col] = make_float2(f10, f11);
                }
                if (cc.Yh) {
                    __half2 h0 = __floats2half2_rn(f00, f01);
                    __half2 h1 = __floats2half2_rn(f10, f11);
                    *(__half2*)&cc.Yh[(size_t)rr * SSZ + col]       = h0;
                    *(__half2*)&cc.Yh[(size_t)(rr + 8) * SSZ + col] = h1;
                }
            }
        }
    }
}

// ===========================================================================
// Tensor-core attention v3: 2 CTAs per head (M-split), causal-aware.
// Even CTA (rows 0-63): all score cols >=64 are masked, so it
//   - skips K-tile rows >=64 in loads,
//   - skips phase-1 LDSM/MMA for warps wn>=2 (their acc stays 0; the
//     writeback mask for those cols is acc-independent),
//   - loads only V rows e<64 and halves the phase-2 ks loop (P cols 64-127
//     are exactly 0 after softmax of -1e30).
// ===========================================================================
#define ATT_STAGE 24576
#define ATT_OFF_V 32768
#define ATT_OFF_P 98304
#define ATT_SMEM  114688

__global__ __launch_bounds__(256, 2) void attn_tc2(
    const __half* __restrict__ Qh, const __half* __restrict__ Kh,
    const __half* __restrict__ Vh, __half* __restrict__ OT)
{
    extern __shared__ char smem[];
    const uint32_t sb = smem_u32(smem);
    float*  scores = (float*)smem;
    __half* Pp     = (__half*)(smem + ATT_OFF_P);
    const uint32_t Pb = sb + ATT_OFF_P;

    const int cta   = blockIdx.x;
    const int bh    = cta >> 1;
    const int m0    = (cta & 1) * 64;
    const bool full = (m0 != 0);         // odd CTA needs all 128 cols
    const int b_ = bh >> 5, h_ = bh & 31;
    const size_t hb = ((size_t)b_ * CH + (size_t)h_ * HD) * SSZ;
    const __half* q = Qh + hb + (size_t)m0 * SSZ;
    const __half* k = Kh + hb;
    const __half* v = Vh + hb;
    __half* oT = OT + (size_t)b_ * SSZ * CH + h_ * HD + m0;

    const int t    = threadIdx.x;
    const int lane = t & 31;
    const int wid  = t >> 5;
    const int wm   = wid >> 2;
    const int wn   = wid & 3;
    const int lr = t >> 3;
    const int lc = t & 7;

    float acc[2][4][4];
#pragma unroll
    for (int mt = 0; mt < 2; mt++)
#pragma unroll
        for (int nt = 0; nt < 4; nt++)
#pragma unroll
            for (int x = 0; x < 4; x++) acc[mt][nt][x] = 0.0f;

    auto issue1 = [&](int chunk) {
        const int stage = chunk % 3;
        const int k0 = chunk * 64;
        const uint32_t As = sb + stage * ATT_STAGE;
        const uint32_t Bs = As + 8192;
#pragma unroll
        for (int it = 0; it < 2; it++) {
            int m = it * 32 + lr;
            cp16(As + (uint32_t)(m * 128 + ((lc ^ (m & 7)) << 4)),
                 q + (size_t)m * SSZ + k0 + lc * 8);
        }
#pragma unroll
        for (int it = 0; it < 4; it++) {
            int n = it * 32 + lr;
            if (full || it < 2)      // even CTA: K rows >=64 unused
                cp16(Bs + (uint32_t)(n * 128 + ((lc ^ (n & 7)) << 4)),
                     k + (size_t)n * SSZ + k0 + lc * 8);
        }
        CP_COMMIT();
    };
    issue1(0); issue1(1); issue1(2);

    const bool p1_active = full || (wn < 2);

    for (int i = 0; i < 32; i++) {
        CP_WAIT(2);
        __syncthreads();
        const uint32_t As = sb + (i % 3) * ATT_STAGE;
        const uint32_t Bs = As + 8192;
        if (p1_active) {
#pragma unroll
            for (int ks = 0; ks < 4; ks++) {
                uint32_t a[2][4], b[2][4];
#pragma unroll
                for (int mt = 0; mt < 2; mt++) {
                    int row = wm * 32 + mt * 16 + (lane & 15);
                    int ch  = ks * 2 + (lane >> 4);
                    ldsm_x4(a[mt][0], a[mt][1], a[mt][2], a[mt][3],
                            As + row * 128 + ((ch ^ (row & 7)) << 4));
                }
#pragma unroll
                for (int p = 0; p < 2; p++) {
                    int row = wn * 32 + p * 16 + ((lane >> 4) << 3) + (lane & 7);
                    int ch  = ks * 2 + ((lane >> 3) & 1);
                    ldsm_x4(b[p][0], b[p][1], b[p][2], b[p][3],
                            Bs + row * 128 + ((ch ^ (row & 7)) << 4));
                }
#pragma unroll
                for (int mt = 0; mt < 2; mt++)
#pragma unroll
                    for (int nt = 0; nt < 4; nt++)
                        mma_f16(acc[mt][nt], a[mt], &b[nt >> 1][(nt & 1) * 2]);
            }
        }
        __syncthreads();
        if (i + 3 < 32) issue1(i + 3);
        else CP_COMMIT();
    }
    CP_WAIT(0);
    __syncthreads();

    {
        const float scale = rsqrtf((float)SSZ);
        const int r = lane >> 2;
        const int c = lane & 3;
#pragma unroll
        for (int mt = 0; mt < 2; mt++) {
            int row0 = wm * 32 + mt * 16 + r;
            int row1 = row0 + 8;
            int g0 = m0 + row0, g1 = m0 + row1;
#pragma unroll
            for (int nt = 0; nt < 4; nt++) {
                int col = wn * 32 + nt * 8 + c * 2;
                scores[row0 * 128 + col]     = (col     <= g0) ? acc[mt][nt][0] * scale : -1e30f;
                scores[row0 * 128 + col + 1] = (col + 1 <= g0) ? acc[mt][nt][1] * scale : -1e30f;
                scores[row1 * 128 + col]     = (col     <= g1) ? acc[mt][nt][2] * scale : -1e30f;
                scores[row1 * 128 + col + 1] = (col + 1 <= g1) ? acc[mt][nt][3] * scale : -1e30f;
            }
        }
    }
    __syncthreads();

    auto issueV = [&](int nc) {
        const uint32_t Vb = sb + ATT_OFF_V + (nc & 1) * 32768;
        const int n0 = nc * 128;
#pragma unroll
        for (int i = 0; i < 8; i++) {
            if (!full && i >= 4) break;   // even CTA: V rows e>=64 unused
            int idx = i * 256 + t;
            int e = idx >> 4;
            int c = idx & 15;
            cp16(Vb + (uint32_t)(e * 256 + ((c ^ (e & 7)) << 4)),
                 v + (size_t)e * SSZ + n0 + c * 8);
        }
        CP_COMMIT();
    };
    issueV(0);

#pragma unroll
    for (int rr = 0; rr < 8; rr++) {
        int row = wid * 8 + rr;
        float v0 = scores[row * 128 + lane];
        float v1 = scores[row * 128 + lane + 32];
        float v2 = scores[row * 128 + lane + 64];
        float v3 = scores[row * 128 + lane + 96];
        float mx = fmaxf(fmaxf(v0, v1), fmaxf(v2, v3));
#pragma unroll
        for (int o = 16; o > 0; o >>= 1)
            mx = fmaxf(mx, __shfl_xor_sync(0xFFFFFFFFu, mx, o));
        float e0 = __expf(v0 - mx), e1 = __expf(v1 - mx);
        float e2 = __expf(v2 - mx), e3 = __expf(v3 - mx);
        float sm = e0 + e1 + e2 + e3;
#pragma unroll
        for (int o = 16; o > 0; o >>= 1)
            sm += __shfl_xor_sync(0xFFFFFFFFu, sm, o);
        float inv = 1.0f / sm;
        float ev[4] = {e0, e1, e2, e3};
#pragma unroll
        for (int j = 0; j < 4; j++) {
            int col = lane + 32 * j;
            int hidx = row * 128 + ((((col >> 3) ^ (row & 7))) << 3) + (col & 7);
            Pp[hidx] = __float2half_rn(ev[j] * inv);
        }
    }

    __half* OTp = (__half*)smem;
    const int kmax = full ? 8 : 4;   // even CTA: P cols 64-127 are exactly 0

    for (int nc = 0; nc < 16; nc++) {
        if (nc + 1 < 16) { issueV(nc + 1); CP_WAIT(1); }
        else             { CP_WAIT(0); }
        __syncthreads();

        const uint32_t Vb = sb + ATT_OFF_V + (nc & 1) * 32768;
        float acc2[2][4][4];
#pragma unroll
        for (int mt = 0; mt < 2; mt++)
#pragma unroll
            for (int nt = 0; nt < 4; nt++)
#pragma unroll
                for (int x = 0; x < 4; x++) acc2[mt][nt][x] = 0.0f;

#pragma unroll
        for (int ks = 0; ks < 8; ks++) {
            if (ks >= kmax) break;
            uint32_t a[2][4], b[2][4];
#pragma unroll
            for (int mt = 0; mt < 2; mt++) {
                int row = wm * 32 + mt * 16 + (lane & 15);
                int ch  = ks * 2 + (lane >> 4);
                ldsm_x4(a[mt][0], a[mt][1], a[mt][2], a[mt][3],
                        Pb + row * 256 + ((ch ^ (row & 7)) << 4));
            }
#pragma unroll
            for (int p = 0; p < 2; p++) {
                int nb  = wn * 32 + p * 16;
                int grp = lane >> 3;
                int li  = lane & 7;
                int e   = ks * 16 + ((grp & 1) << 3) + li;
                int ncol = nb + ((grp >> 1) << 3);
                ldsm_x4_t(b[p][0], b[p][1], b[p][2], b[p][3],
                          Vb + e * 256 + (((ncol >> 3) ^ (e & 7)) << 4));
            }
#pragma unroll
            for (int mt = 0; mt < 2; mt++)
#pragma unroll
                for (int nt = 0; nt < 4; nt++)
                    mma_f16(acc2[mt][nt], a[mt], &b[nt >> 1][(nt & 1) * 2]);
        }

        {
            const int r = lane >> 2;
            const int c = lane & 3;
#pragma unroll
            for (int mt = 0; mt < 2; mt++) {
                int row0 = wm * 32 + mt * 16 + r;
#pragma unroll
                for (int nt = 0; nt < 4; nt++) {
                    int col = wn * 32 + nt * 8 + c * 2;
                    OTp[col * 64 + row0]           = __float2half_rn(acc2[mt][nt][0]);
                    OTp[(col + 1) * 64 + row0]     = __float2half_rn(acc2[mt][nt][1]);
                    OTp[col * 64 + row0 + 8]       = __float2half_rn(acc2[mt][nt][2]);
                    OTp[(col + 1) * 64 + row0 + 8] = __float2half_rn(acc2[mt][nt][3]);
                }
            }
        }
        __syncthreads();

        {
            int s  = t >> 1;
            int dp = (t & 1) * 32;
            const uint4* src = (const uint4*)(OTp + s * 64 + dp);
            uint4* dst = (uint4*)(oT + (size_t)(nc * 128 + s) * CH + dp);
#pragma unroll
            for (int u = 0; u < 4; u++) dst[u] = src[u];
        }
        __syncthreads();
    }
}

// ===========================================================================
// Launch
// ===========================================================================
extern "C" void kernel_launch(void* const* d_in, const int* in_sizes, int n_in,
                              void* d_out, int out_size)
{
    const float* hs = (const float*)d_in[0];
    const float* Wq = (const float*)d_in[1];
    const float* bq = (const float*)d_in[2];
    const float* Wk = (const float*)d_in[3];
    const float* bk = (const float*)d_in[4];
    const float* Wv = (const float*)d_in[5];
    const float* bv = (const float*)d_in[6];
    const float* Wo = (const float*)d_in[7];
    const float* bo = (const float*)d_in[8];

    float *kfb, *vfb;
    __half *qh, *kh, *vh, *atbufh, *xth, *wh;
    cudaGetSymbolAddress((void**)&qh,     g_qh);
    cudaGetSymbolAddress((void**)&kh,     g_kh);
    cudaGetSymbolAddress((void**)&vh,     g_vh);
    cudaGetSymbolAddress((void**)&atbufh, g_attnTh);
    cudaGetSymbolAddress((void**)&xth,    g_xth);
    cudaGetSymbolAddress((void**)&wh,     g_wh);
    cudaGetSymbolAddress((void**)&kfb,    g_kfb);
    cudaGetSymbolAddress((void**)&vfb,    g_vfb);

    float* out = (float*)d_out;
    float* kout;
    float* vout;
    if ((long long)out_size >= 3LL * BHS) {
        kout = out + (size_t)BHS;
        vout = out + 2 * (size_t)BHS;
    } else {
        kout = kfb;
        vout = vfb;
    }

    int sms = 148;
    cudaDeviceGetAttribute(&sms, cudaDevAttrMultiProcessorCount, 0);
    const int pgrid = 2 * sms;

    // ---- Prep ----
    round_half4_kernel<<<dim3(WSZ / (256 * 8), 4), 256>>>(Wq, Wk, Wv, Wo, wh);
    transpose_half_kernel<<<dim3(SSZ / 32, CH / 64, BB), 256>>>(hs, xth);

    // ---- Persistent Q/K/V projections (6144 tiles) ----
    cudaFuncSetAttribute(gemm_persist,
                         cudaFuncAttributeMaxDynamicSharedMemorySize, SMEM_G);
    gemm_persist<<<pgrid, 128, SMEM_G>>>(
        wh, xth, bq, bk, bv, qh, kout, kh, vout, vh, 0, 6144);

    // ---- Tensor-core attention (2 CTAs per head, causal-aware) ----
    cudaFuncSetAttribute(attn_tc2,
                         cudaFuncAttributeMaxDynamicSharedMemorySize, ATT_SMEM);
    attn_tc2<<<BB * NH * 2, 256, ATT_SMEM>>>(qh, kh, vh, atbufh);

    // ---- Persistent output projection (2048 tiles) ----
    gemm_persist<<<pgrid, 128, SMEM_G>>>(
        wh + 3 * (size_t)WSZ, atbufh, bo, (const float*)0, (const float*)0,
        (__half*)0, out, (__half*)0, (float*)0, (__half*)0, 1, 2048);
}

// round 12
// speedup vs baseline: 1.2053x; 1.0192x over previous
#include <cuda_runtime.h>
#include <cuda_fp16.h>
#include <math.h>
#include <stdint.h>

// Problem constants
#define BB 4
#define CH 4096     // HID
#define SSZ 2048    // S
#define NH 32       // heads
#define HD 128      // head dim

#define BHS 33554432   // BB*CH*SSZ elements
#define WSZ 16777216   // CH*CH elements

// Scratch (allocation-free rule: __device__ globals)
__device__ __half g_qh[BHS];      // Q half [b][ch][s]
__device__ __half g_kh[BHS];      // K half [b][ch][s]
__device__ __half g_vh[BHS];      // V half [b][ch][s]
__device__ __half g_attnTh[BHS];  // attention out, transposed half [b][s][ch]
__device__ __half g_xth[BHS];     // hidden transposed half [b][s][ch]
__device__ __half g_wh[4 * WSZ];  // half Wq,Wk,Wv,Wo (row-major, K-contig)
__device__ float  g_kfb[BHS];     // fallback K dest
__device__ float  g_vfb[BHS];     // fallback V dest

// ===========================================================================
// Helpers
// ===========================================================================
__device__ __forceinline__ uint32_t smem_u32(const void* p) {
    uint32_t a;
    asm("{ .reg .u64 t; cvta.to.shared.u64 t, %1; cvt.u32.u64 %0, t; }"
        : "=r"(a) : "l"(p));
    return a;
}

__device__ __forceinline__ void cp16(uint32_t dst, const void* src) {
    asm volatile("cp.async.cg.shared.global [%0], [%1], 16;"
                 :: "r"(dst), "l"(src) : "memory");
}
#define CP_COMMIT() asm volatile("cp.async.commit_group;" ::: "memory")
#define CP_WAIT(n)  asm volatile("cp.async.wait_group %0;" :: "n"(n) : "memory")

__device__ __forceinline__ void ldsm_x4(uint32_t& r0, uint32_t& r1,
                                        uint32_t& r2, uint32_t& r3, uint32_t addr) {
    asm volatile("ldmatrix.sync.aligned.m8n8.x4.shared.b16 {%0,%1,%2,%3}, [%4];"
                 : "=r"(r0), "=r"(r1), "=r"(r2), "=r"(r3) : "r"(addr));
}

__device__ __forceinline__ void ldsm_x4_t(uint32_t& r0, uint32_t& r1,
                                          uint32_t& r2, uint32_t& r3, uint32_t addr) {
    asm volatile("ldmatrix.sync.aligned.m8n8.x4.trans.shared.b16 {%0,%1,%2,%3}, [%4];"
                 : "=r"(r0), "=r"(r1), "=r"(r2), "=r"(r3) : "r"(addr));
}

// mma m16n8k16 f16 inputs, f32 accumulate
__device__ __forceinline__ void mma_f16(float* d, const uint32_t* a, const uint32_t* b) {
    asm volatile(
        "mma.sync.aligned.m16n8k16.row.col.f32.f16.f16.f32 "
        "{%0,%1,%2,%3}, {%4,%5,%6,%7}, {%8,%9}, {%0,%1,%2,%3};"
        : "+f"(d[0]), "+f"(d[1]), "+f"(d[2]), "+f"(d[3])
        : "r"(a[0]), "r"(a[1]), "r"(a[2]), "r"(a[3]), "r"(b[0]), "r"(b[1]));
}

// ===========================================================================
// Merged prep: blocks [0, 32768) convert W fp32->half; blocks [32768, 49152)
// transpose+convert X. Co-running both fills DRAM BW through ramps/tails.
// ===========================================================================
#define PREP_WBLKS 32768   // 4 weights x 8192
#define PREP_TBLKS 16384   // 4 batches x 64ch-tiles x 64s-tiles
#define PREP_BLKS  (PREP_WBLKS + PREP_TBLKS)

__global__ void prep_kernel(
    const float* __restrict__ W0, const float* __restrict__ W1,
    const float* __restrict__ W2, const float* __restrict__ W3,
    __half* __restrict__ Wh,
    const float* __restrict__ X, __half* __restrict__ Xt)
{
    __shared__ float tile[32][66];
    const int bx = blockIdx.x;
    if (bx < PREP_WBLKS) {
        const int widx = bx >> 13;            // 0..3
        const int blk  = bx & 8191;
        const float* W = (widx == 0) ? W0 : (widx == 1) ? W1
                       : (widx == 2) ? W2 : W3;
        __half* dst = Wh + (size_t)widx * WSZ;
        size_t i = ((size_t)blk * 256 + threadIdx.x) * 8;
        float4 v0 = *(const float4*)(W + i);
        float4 v1 = *(const float4*)(W + i + 4);
        __half2 h0 = __floats2half2_rn(v0.x, v0.y);
        __half2 h1 = __floats2half2_rn(v0.z, v0.w);
        __half2 h2 = __floats2half2_rn(v1.x, v1.y);
        __half2 h3 = __floats2half2_rn(v1.z, v1.w);
        uint4 o;
        o.x = *(uint32_t*)&h0; o.y = *(uint32_t*)&h1;
        o.z = *(uint32_t*)&h2; o.w = *(uint32_t*)&h3;
        *(uint4*)(dst + i) = o;
    } else {
        const int tb  = bx - PREP_WBLKS;
        const int b   = tb >> 12;             // 0..3
        const int rem = tb & 4095;
        const int k0  = (rem >> 6) * 64;      // ch tile
        const int n0  = (rem & 63) * 32;      // s tile
        const float* Xb  = X  + (size_t)b * CH * SSZ;
        __half*      Xtb = Xt + (size_t)b * SSZ * CH;
        const int lane = threadIdx.x & 31;
        const int w    = threadIdx.x >> 5;
#pragma unroll
        for (int i = 0; i < 8; i++) {
            int ch = w * 8 + i;
            tile[lane][ch] = Xb[(size_t)(k0 + ch) * SSZ + n0 + lane];
        }
        __syncthreads();
#pragma unroll
        for (int j = 0; j < 4; j++) {
            int s = w * 4 + j;
            float2 v = *(const float2*)&tile[s][lane * 2];
            __half2 h = __floats2half2_rn(v.x, v.y);
            *(__half2*)&Xtb[(size_t)(n0 + s) * CH + k0 + lane * 2] = h;
        }
    }
}

// ===========================================================================
// Persistent fp16 tensor-core GEMM — single-barrier mainloop; cp.async issue
// moved to immediately after the barrier (before compute) so next-next
// chunk's loads launch one compute-block earlier. Safety: barrier i proves
// all warps finished compute i-1 (stage (i+2)%3), the stage being written.
// ===========================================================================
#define STAGE_B 32768
#define SMEM_G  (3 * STAGE_B)   // 98304

struct TileCtx {
    const __half* A;
    const __half* B;
    const float*  bias;
    float*  Yf;
    __half* Yh;
};

__global__ __launch_bounds__(128, 2) void gemm_persist(
    const __half* __restrict__ Wbase, const __half* __restrict__ Bbase,
    const float* __restrict__ b0, const float* __restrict__ b1,
    const float* __restrict__ b2,
    __half* __restrict__ H0, float* __restrict__ F1, __half* __restrict__ H1,
    float* __restrict__ F2, __half* __restrict__ H2,
    int mode, int ntiles)
{
    extern __shared__ char smem[];
    const uint32_t sb = smem_u32(smem);
    const int t    = threadIdx.x;
    const int lane = t & 31;
    const int wid  = t >> 5;
    const int wm   = wid >> 1;
    const int wn   = wid & 1;
    const int lr = t >> 3;
    const int lc = t & 7;

    auto decode = [&](int idx, TileCtx& c) {
        int x  = idx & 15;
        int n0 = x << 7;
        if (mode == 0) {
            int r = idx >> 4;
            int y = r % 96;
            int z = r / 96;
            int widx = y >> 5;
            int m0 = (y & 31) << 7;
            c.A = Wbase + (size_t)widx * WSZ + (size_t)m0 * CH;
            c.B = Bbase + (size_t)z * SSZ * CH + (size_t)n0 * CH;
            c.bias = ((widx == 0) ? b0 : (widx == 1) ? b1 : b2) + m0;
            size_t o = (size_t)z * CH * SSZ + (size_t)m0 * SSZ + n0;
            c.Yf = (widx == 0) ? (float*)0 : (((widx == 1) ? F1 : F2) + o);
            c.Yh = ((widx == 0) ? H0 : (widx == 1) ? H1 : H2) + o;
        } else {
            int y = (idx >> 4) & 31;
            int z = idx >> 9;
            int m0 = y << 7;
            c.A = Wbase + (size_t)m0 * CH;
            c.B = Bbase + (size_t)z * SSZ * CH + (size_t)n0 * CH;
            c.bias = b0 + m0;
            c.Yf = F1 + (size_t)z * CH * SSZ + (size_t)m0 * SSZ + n0;
            c.Yh = (__half*)0;
        }
    };

    TileCtx ictx;
    int itile  = blockIdx.x;
    int ichunk = 0;
    int istage = 0;
    bool ivalid = (itile < ntiles);
    if (ivalid) decode(itile, ictx);

    auto issue = [&]() {
        if (ivalid) {
            const int k0 = ichunk * 64;
            const uint32_t As = sb + istage * STAGE_B;
            const uint32_t Bs = As + 16384;
#pragma unroll
            for (int it = 0; it < 8; it++) {
                int m = it * 16 + lr;
                cp16(As + (uint32_t)(m * 128 + ((lc ^ (m & 7)) << 4)),
                     ictx.A + (size_t)m * CH + k0 + lc * 8);
            }
#pragma unroll
            for (int it = 0; it < 8; it++) {
                int n = it * 16 + lr;
                cp16(Bs + (uint32_t)(n * 128 + ((lc ^ (n & 7)) << 4)),
                     ictx.B + (size_t)n * CH + k0 + lc * 8);
            }
            istage = (istage == 2) ? 0 : istage + 1;
            if (++ichunk == 64) {
                ichunk = 0;
                itile += gridDim.x;
                ivalid = (itile < ntiles);
                if (ivalid) decode(itile, ictx);
            }
        }
        CP_COMMIT();
    };

    issue(); issue();    // depth-2 prefetch
    int cstage = 0;

    for (int tt = blockIdx.x; tt < ntiles; tt += gridDim.x) {
        TileCtx cc;
        decode(tt, cc);

        float acc[4][8][4];
#pragma unroll
        for (int mt = 0; mt < 4; mt++)
#pragma unroll
            for (int nt = 0; nt < 8; nt++)
#pragma unroll
                for (int x = 0; x < 4; x++) acc[mt][nt][x] = 0.0f;

        for (int i = 0; i < 64; i++) {
            CP_WAIT(1);
            __syncthreads();        // single barrier per iteration
            issue();                // stage (i+2)%3 freed by the barrier above
            const uint32_t As = sb + cstage * STAGE_B;
            const uint32_t Bs = As + 16384;
#pragma unroll
            for (int ks = 0; ks < 4; ks++) {
                uint32_t a[4][4], b[4][4];
#pragma unroll
                for (int mt = 0; mt < 4; mt++) {
                    int row = wm * 64 + mt * 16 + (lane & 15);
                    int ch  = ks * 2 + (lane >> 4);
                    ldsm_x4(a[mt][0], a[mt][1], a[mt][2], a[mt][3],
                            As + row * 128 + ((ch ^ (row & 7)) << 4));
                }
#pragma unroll
                for (int p = 0; p < 4; p++) {
                    int row = wn * 64 + p * 16 + ((lane >> 4) << 3) + (lane & 7);
                    int ch  = ks * 2 + ((lane >> 3) & 1);
                    ldsm_x4(b[p][0], b[p][1], b[p][2], b[p][3],
                            Bs + row * 128 + ((ch ^ (row & 7)) << 4));
                }
#pragma unroll
                for (int mt = 0; mt < 4; mt++)
#pragma unroll
                    for (int nt = 0; nt < 8; nt++)
                        mma_f16(acc[mt][nt], a[mt], &b[nt >> 1][(nt & 1) * 2]);
            }
            cstage = (cstage == 2) ? 0 : cstage + 1;
        }

        const int r  = lane >> 2;
        const int c4 = lane & 3;
#pragma unroll
        for (int mt = 0; mt < 4; mt++) {
            int rr = wm * 64 + mt * 16 + r;
            float bv0 = cc.bias[rr];
            float bv1 = cc.bias[rr + 8];
#pragma unroll
            for (int nt = 0; nt < 8; nt++) {
                int col = wn * 64 + nt * 8 + c4 * 2;
                float f00 = acc[mt][nt][0] + bv0, f01 = acc[mt][nt][1] + bv0;
                float f10 = acc[mt][nt][2] + bv1, f11 = acc[mt][nt][3] + bv1;
                if (cc.Yf) {
                    *(float2*)&cc.Yf[(size_t)rr * SSZ + col]       = make_float2(f00, f01);
                    *(float2*)&cc.Yf[(size_t)(rr + 8) * SSZ + col] = make_float2(f10, f11);
                }
                if (cc.Yh) {
                    __half2 h0 = __floats2half2_rn(f00, f01);
                    __half2 h1 = __floats2half2_rn(f10, f11);
                    *(__half2*)&cc.Yh[(size_t)rr * SSZ + col]       = h0;
                    *(__half2*)&cc.Yh[(size_t)(rr + 8) * SSZ + col] = h1;
                }
            }
        }
    }
}

// ===========================================================================
// Tensor-core attention v3 (R11) + double-buffered OT staging (one fewer
// barrier per phase-2 chunk: STG of buf b overlaps next chunk's STS to 1-b).
// ===========================================================================
#define ATT_STAGE 24576
#define ATT_OFF_V 32768
#define ATT_OFF_P 98304
#define ATT_SMEM  114688

__global__ __launch_bounds__(256, 2) void attn_tc2(
    const __half* __restrict__ Qh, const __half* __restrict__ Kh,
    const __half* __restrict__ Vh, __half* __restrict__ OT)
{
    extern __shared__ char smem[];
    const uint32_t sb = smem_u32(smem);
    float*  scores = (float*)smem;
    __half* Pp     = (__half*)(smem + ATT_OFF_P);
    const uint32_t Pb = sb + ATT_OFF_P;

    const int cta   = blockIdx.x;
    const int bh    = cta >> 1;
    const int m0    = (cta & 1) * 64;
    const bool full = (m0 != 0);
    const int b_ = bh >> 5, h_ = bh & 31;
    const size_t hb = ((size_t)b_ * CH + (size_t)h_ * HD) * SSZ;
    const __half* q = Qh + hb + (size_t)m0 * SSZ;
    const __half* k = Kh + hb;
    const __half* v = Vh + hb;
    __half* oT = OT + (size_t)b_ * SSZ * CH + h_ * HD + m0;

    const int t    = threadIdx.x;
    const int lane = t & 31;
    const int wid  = t >> 5;
    const int wm   = wid >> 2;
    const int wn   = wid & 3;
    const int lr = t >> 3;
    const int lc = t & 7;

    float acc[2][4][4];
#pragma unroll
    for (int mt = 0; mt < 2; mt++)
#pragma unroll
        for (int nt = 0; nt < 4; nt++)
#pragma unroll
            for (int x = 0; x < 4; x++) acc[mt][nt][x] = 0.0f;

    auto issue1 = [&](int chunk) {
        const int stage = chunk % 3;
        const int k0 = chunk * 64;
        const uint32_t As = sb + stage * ATT_STAGE;
        const uint32_t Bs = As + 8192;
#pragma unroll
        for (int it = 0; it < 2; it++) {
            int m = it * 32 + lr;
            cp16(As + (uint32_t)(m * 128 + ((lc ^ (m & 7)) << 4)),
                 q + (size_t)m * SSZ + k0 + lc * 8);
        }
#pragma unroll
        for (int it = 0; it < 4; it++) {
            int n = it * 32 + lr;
            if (full || it < 2)
                cp16(Bs + (uint32_t)(n * 128 + ((lc ^ (n & 7)) << 4)),
                     k + (size_t)n * SSZ + k0 + lc * 8);
        }
        CP_COMMIT();
    };
    issue1(0); issue1(1); issue1(2);

    const bool p1_active = full || (wn < 2);

    for (int i = 0; i < 32; i++) {
        CP_WAIT(2);
        __syncthreads();
        const uint32_t As = sb + (i % 3) * ATT_STAGE;
        const uint32_t Bs = As + 8192;
        if (p1_active) {
#pragma unroll
            for (int ks = 0; ks < 4; ks++) {
                uint32_t a[2][4], b[2][4];
#pragma unroll
                for (int mt = 0; mt < 2; mt++) {
                    int row = wm * 32 + mt * 16 + (lane & 15);
                    int ch  = ks * 2 + (lane >> 4);
                    ldsm_x4(a[mt][0], a[mt][1], a[mt][2], a[mt][3],
                            As + row * 128 + ((ch ^ (row & 7)) << 4));
                }
#pragma unroll
                for (int p = 0; p < 2; p++) {
                    int row = wn * 32 + p * 16 + ((lane >> 4) << 3) + (lane & 7);
                    int ch  = ks * 2 + ((lane >> 3) & 1);
                    ldsm_x4(b[p][0], b[p][1], b[p][2], b[p][3],
                            Bs + row * 128 + ((ch ^ (row & 7)) << 4));
                }
#pragma unroll
                for (int mt = 0; mt < 2; mt++)
#pragma unroll
                    for (int nt = 0; nt < 4; nt++)
                        mma_f16(acc[mt][nt], a[mt], &b[nt >> 1][(nt & 1) * 2]);
            }
        }
        __syncthreads();
        if (i + 3 < 32) issue1(i + 3);
        else CP_COMMIT();
    }
    CP_WAIT(0);
    __syncthreads();

    {
        const float scale = rsqrtf((float)SSZ);
        const int r = lane >> 2;
        const int c = lane & 3;
#pragma unroll
        for (int mt = 0; mt < 2; mt++) {
            int row0 = wm * 32 + mt * 16 + r;
            int row1 = row0 + 8;
            int g0 = m0 + row0, g1 = m0 + row1;
#pragma unroll
            for (int nt = 0; nt < 4; nt++) {
                int col = wn * 32 + nt * 8 + c * 2;
                scores[row0 * 128 + col]     = (col     <= g0) ? acc[mt][nt][0] * scale : -1e30f;
                scores[row0 * 128 + col + 1] = (col + 1 <= g0) ? acc[mt][nt][1] * scale : -1e30f;
                scores[row1 * 128 + col]     = (col     <= g1) ? acc[mt][nt][2] * scale : -1e30f;
                scores[row1 * 128 + col + 1] = (col + 1 <= g1) ? acc[mt][nt][3] * scale : -1e30f;
            }
        }
    }
    __syncthreads();

    auto issueV = [&](int nc) {
        const uint32_t Vb = sb + ATT_OFF_V + (nc & 1) * 32768;
        const int n0 = nc * 128;
#pragma unroll
        for (int i = 0; i < 8; i++) {
            if (!full && i >= 4) break;
            int idx = i * 256 + t;
            int e = idx >> 4;
            int c = idx & 15;
            cp16(Vb + (uint32_t)(e * 256 + ((c ^ (e & 7)) << 4)),
                 v + (size_t)e * SSZ + n0 + c * 8);
        }
        CP_COMMIT();
    };
    issueV(0);

#pragma unroll
    for (int rr = 0; rr < 8; rr++) {
        int row = wid * 8 + rr;
        float v0 = scores[row * 128 + lane];
        float v1 = scores[row * 128 + lane + 32];
        float v2 = scores[row * 128 + lane + 64];
        float v3 = scores[row * 128 + lane + 96];
        float mx = fmaxf(fmaxf(v0, v1), fmaxf(v2, v3));
#pragma unroll
        for (int o = 16; o > 0; o >>= 1)
            mx = fmaxf(mx, __shfl_xor_sync(0xFFFFFFFFu, mx, o));
        float e0 = __expf(v0 - mx), e1 = __expf(v1 - mx);
        float e2 = __expf(v2 - mx), e3 = __expf(v3 - mx);
        float sm = e0 + e1 + e2 + e3;
#pragma unroll
        for (int o = 16; o > 0; o >>= 1)
            sm += __shfl_xor_sync(0xFFFFFFFFu, sm, o);
        float inv = 1.0f / sm;
        float ev[4] = {e0, e1, e2, e3};
#pragma unroll
        for (int j = 0; j < 4; j++) {
            int col = lane + 32 * j;
            int hidx = row * 128 + ((((col >> 3) ^ (row & 7))) << 3) + (col & 7);
            Pp[hidx] = __float2half_rn(ev[j] * inv);
        }
    }

    const int kmax = full ? 8 : 4;

    for (int nc = 0; nc < 16; nc++) {
        __half* OTp = (__half*)(smem + (nc & 1) * 16384);   // double-buffered
        if (nc + 1 < 16) { issueV(nc + 1); CP_WAIT(1); }
        else             { CP_WAIT(0); }
        __syncthreads();   // V[nc] arrived; prior STG from this buffer done

        const uint32_t Vb = sb + ATT_OFF_V + (nc & 1) * 32768;
        float acc2[2][4][4];
#pragma unroll
        for (int mt = 0; mt < 2; mt++)
#pragma unroll
            for (int nt = 0; nt < 4; nt++)
#pragma unroll
                for (int x = 0; x < 4; x++) acc2[mt][nt][x] = 0.0f;

#pragma unroll
        for (int ks = 0; ks < 8; ks++) {
            if (ks >= kmax) break;
            uint32_t a[2][4], b[2][4];
#pragma unroll
            for (int mt = 0; mt < 2; mt++) {
                int row = wm * 32 + mt * 16 + (lane & 15);
                int ch  = ks * 2 + (lane >> 4);
                ldsm_x4(a[mt][0], a[mt][1], a[mt][2], a[mt][3],
                        Pb + row * 256 + ((ch ^ (row & 7)) << 4));
            }
#pragma unroll
            for (int p = 0; p < 2; p++) {
                int nb  = wn * 32 + p * 16;
                int grp = lane >> 3;
                int li  = lane & 7;
                int e   = ks * 16 + ((grp & 1) << 3) + li;
                int ncol = nb + ((grp >> 1) << 3);
                ldsm_x4_t(b[p][0], b[p][1], b[p][2], b[p][3],
                          Vb + e * 256 + (((ncol >> 3) ^ (e & 7)) << 4));
            }
#pragma unroll
            for (int mt = 0; mt < 2; mt++)
#pragma unroll
                for (int nt = 0; nt < 4; nt++)
                    mma_f16(acc2[mt][nt], a[mt], &b[nt >> 1][(nt & 1) * 2]);
        }

        {
            const int r = lane >> 2;
            const int c = lane & 3;
#pragma unroll
            for (int mt = 0; mt < 2; mt++) {
                int row0 = wm * 32 + mt * 16 + r;
#pragma unroll
                for (int nt = 0; nt < 4; nt++) {
                    int col = wn * 32 + nt * 8 + c * 2;
                    OTp[col * 64 + row0]           = __float2half_rn(acc2[mt][nt][0]);
                    OTp[(col + 1) * 64 + row0]     = __float2half_rn(acc2[mt][nt][1]);
                    OTp[col * 64 + row0 + 8]       = __float2half_rn(acc2[mt][nt][2]);
                    OTp[(col + 1) * 64 + row0 + 8] = __float2half_rn(acc2[mt][nt][3]);
                }
            }
        }
        __syncthreads();   // OTp complete before STG

        {
            int s  = t >> 1;
            int dp = (t & 1) * 32;
            const uint4* src = (const uint4*)(OTp + s * 64 + dp);
            uint4* dst = (uint4*)(oT + (size_t)(nc * 128 + s) * CH + dp);
#pragma unroll
            for (int u = 0; u < 4; u++) dst[u] = src[u];
        }
        // no trailing barrier: next chunk's STS targets the other buffer
    }
}

// ===========================================================================
// Launch
// ===========================================================================
extern "C" void kernel_launch(void* const* d_in, const int* in_sizes, int n_in,
                              void* d_out, int out_size)
{
    const float* hs = (const float*)d_in[0];
    const float* Wq = (const float*)d_in[1];
    const float* bq = (const float*)d_in[2];
    const float* Wk = (const float*)d_in[3];
    const float* bk = (const float*)d_in[4];
    const float* Wv = (const float*)d_in[5];
    const float* bv = (const float*)d_in[6];
    const float* Wo = (const float*)d_in[7];
    const float* bo = (const float*)d_in[8];

    float *kfb, *vfb;
    __half *qh, *kh, *vh, *atbufh, *xth, *wh;
    cudaGetSymbolAddress((void**)&qh,     g_qh);
    cudaGetSymbolAddress((void**)&kh,     g_kh);
    cudaGetSymbolAddress((void**)&vh,     g_vh);
    cudaGetSymbolAddress((void**)&atbufh, g_attnTh);
    cudaGetSymbolAddress((void**)&xth,    g_xth);
    cudaGetSymbolAddress((void**)&wh,     g_wh);
    cudaGetSymbolAddress((void**)&kfb,    g_kfb);
    cudaGetSymbolAddress((void**)&vfb,    g_vfb);

    float* out = (float*)d_out;
    float* kout;
    float* vout;
    if ((long long)out_size >= 3LL * BHS) {
        kout = out + (size_t)BHS;
        vout = out + 2 * (size_t)BHS;
    } else {
        kout = kfb;
        vout = vfb;
    }

    int sms = 148;
    cudaDeviceGetAttribute(&sms, cudaDevAttrMultiProcessorCount, 0);
    const int pgrid = 2 * sms;

    // ---- Merged prep (W convert + X transpose co-run) ----
    prep_kernel<<<PREP_BLKS, 256>>>(Wq, Wk, Wv, Wo, wh, hs, xth);

    // ---- Persistent Q/K/V projections (6144 tiles) ----
    cudaFuncSetAttribute(gemm_persist,
                         cudaFuncAttributeMaxDynamicSharedMemorySize, SMEM_G);
    gemm_persist<<<pgrid, 128, SMEM_G>>>(
        wh, xth, bq, bk, bv, qh, kout, kh, vout, vh, 0, 6144);

    // ---- Tensor-core attention (2 CTAs per head, causal-aware) ----
    cudaFuncSetAttribute(attn_tc2,
                         cudaFuncAttributeMaxDynamicSharedMemorySize, ATT_SMEM);
    attn_tc2<<<BB * NH * 2, 256, ATT_SMEM>>>(qh, kh, vh, atbufh);

    // ---- Persistent output projection (2048 tiles) ----
    gemm_persist<<<pgrid, 128, SMEM_G>>>(
        wh + 3 * (size_t)WSZ, atbufh, bo, (const float*)0, (const float*)0,
        (__half*)0, out, (__half*)0, (float*)0, (__half*)0, 1, 2048);
}